// round 2
// baseline (speedup 1.0000x reference)
#include <cuda_runtime.h>
#include <cuda_bf16.h>
#include <math.h>

// ======================= problem constants =======================
#define L_  1024
#define B_  8
#define D_  512
#define LT_ 32
#define H_  8
#define HD_ 64
#define TOTPOS 2081   // 1024+512+256+128+64+43+32+22

// ======================= scratch (static device memory) =========
__device__ float g_sent[B_*D_];
__device__ float g_scores[B_*L_];
__device__ int   g_vmask[B_*L_];
__device__ int   g_tmask[B_*LT_];
__device__ int   g_ecmask[B_*L_];
__device__ int   g_kmask[TOTPOS*B_];
__device__ float g_keys[TOTPOS*B_*D_];
__device__ float g_qkv[8192*1536];
__device__ float g_q[8192*512];
__device__ float g_k[12288*512];
__device__ float g_v[12288*512];
__device__ float g_attn[8192*512];
__device__ float g_tmp[8192*512];
__device__ float g_xec[8192*512];
__device__ float g_total[8192*512];
__device__ float g_xcc[8192*512];
__device__ float g_sum[8192*512];
__device__ float g_h1[8192*2048];

// ======================= mask dtype conversion ==================
// mask[0][1] is guaranteed True for both masks (vlen>=513, tlen>=16).
// bool/uint8: raw[1]==1 ; int32: raw[0]==1, raw[1]==0 ; float32: raw[0]==0.
__global__ void mask_convert_kernel(const unsigned char* __restrict__ raw,
                                    int* __restrict__ out, int n)
{
    int i = blockIdx.x * blockDim.x + threadIdx.x;
    if (i >= n) return;
    int v;
    if (raw[1] == 1) {                // 1-byte bool
        v = raw[i] != 0;
    } else if (raw[0] == 1) {         // int32
        v = ((const int*)raw)[i] != 0;
    } else {                          // float32
        v = ((const float*)raw)[i] != 0.0f;
    }
    out[i] = v;
}

// ======================= sentence pooling =======================
__global__ void sent_kernel(const float* __restrict__ txt, const int* __restrict__ tmask,
                            const float* __restrict__ wts_w, const float* __restrict__ wts_b,
                            float* __restrict__ sent)
{
    __shared__ float aw[LT_];
    int b = blockIdx.x;
    int t = threadIdx.x;            // 512 threads
    int warp = t >> 5, lane = t & 31;
    for (int tok = warp; tok < LT_; tok += 16) {
        float s = 0.f;
        for (int d = lane; d < D_; d += 32)
            s += txt[((size_t)tok * B_ + b) * D_ + d] * wts_w[d];
        #pragma unroll
        for (int off = 16; off; off >>= 1) s += __shfl_xor_sync(0xffffffffu, s, off);
        if (lane == 0) {
            s += wts_b[0];
            if (!tmask[b * LT_ + tok]) s = -1e9f;
            aw[tok] = s;
        }
    }
    __syncthreads();
    if (t == 0) {
        float mx = -3e38f;
        for (int i = 0; i < LT_; i++) mx = fmaxf(mx, aw[i]);
        float sum = 0.f;
        for (int i = 0; i < LT_; i++) { aw[i] = __expf(aw[i] - mx); sum += aw[i]; }
        float inv = 1.f / sum;
        for (int i = 0; i < LT_; i++) aw[i] *= inv;
    }
    __syncthreads();
    float s = 0.f;
    for (int tok = 0; tok < LT_; tok++)
        s += aw[tok] * txt[((size_t)tok * B_ + b) * D_ + t];
    sent[b * D_ + t] = s;
}

// ======================= relevance scores =======================
__global__ void score_kernel(const float* __restrict__ x, const float* __restrict__ sent,
                             const int* __restrict__ vmask, float* __restrict__ scores)
{
    int l = blockIdx.x, b = blockIdx.y;
    int t = threadIdx.x;            // 128
    __shared__ float r4[4];
    float s = 0.f;
    for (int d = t; d < D_; d += 128)
        s += x[((size_t)l * B_ + b) * D_ + d] * sent[b * D_ + d];
    #pragma unroll
    for (int off = 16; off; off >>= 1) s += __shfl_xor_sync(0xffffffffu, s, off);
    if ((t & 31) == 0) r4[t >> 5] = s;
    __syncthreads();
    if (t == 0) {
        s = r4[0] + r4[1] + r4[2] + r4[3];
        scores[b * L_ + l] = vmask[b * L_ + l] ? s : -1e9f;
    }
}

// ======================= top-k (k=512) via bitonic sort =========
__global__ void topk_kernel(const float* __restrict__ scores, int* __restrict__ ecmask)
{
    __shared__ float sv[L_];
    __shared__ int cnt;
    int b = blockIdx.x, t = threadIdx.x;   // 512 threads
    sv[t] = scores[b * L_ + t];
    sv[t + 512] = scores[b * L_ + t + 512];
    if (t == 0) cnt = 0;
    __syncthreads();
    for (int k = 2; k <= L_; k <<= 1) {
        for (int j = k >> 1; j > 0; j >>= 1) {
            for (int i = t; i < L_; i += 512) {
                int ixj = i ^ j;
                if (ixj > i) {
                    bool up = ((i & k) == 0);   // ascending segment
                    float a = sv[i], c = sv[ixj];
                    if ((a > c) == up) { sv[i] = c; sv[ixj] = a; }
                }
            }
            __syncthreads();
        }
    }
    float thr = sv[512];   // 512th largest (ascending sorted)
    for (int i = t; i < L_; i += 512) {
        float sc = scores[b * L_ + i];
        int ig = 1;
        if (sc > thr) { ig = 0; atomicAdd(&cnt, 1); }
        ecmask[b * L_ + i] = ig;
    }
    __syncthreads();
    if (t == 0) {
        int need = 512 - cnt;
        for (int i = 0; i < L_ && need > 0; i++) {
            if (scores[b * L_ + i] == thr && ecmask[b * L_ + i]) {
                ecmask[b * L_ + i] = 0; need--;
            }
        }
    }
}

// ======================= max-pool keys ==========================
// keys[(posoff+p)*B+b][d] = max over window (zero-padded past L)
__global__ void pool_kernel(const float* __restrict__ x, const int* __restrict__ vmask,
                            float* __restrict__ keys, int* __restrict__ kmask,
                            int s, int posoff)
{
    int p = blockIdx.x, b = blockIdx.y, d = threadIdx.x;  // 512 threads
    int l0 = p * s;
    float mx = (l0 + s > L_) ? 0.0f : -3.0e38f;  // zero-pad participates in max
    int lend = l0 + s; if (lend > L_) lend = L_;
    for (int l = l0; l < lend; l++)
        mx = fmaxf(mx, x[((size_t)l * B_ + b) * D_ + d]);
    keys[((size_t)(posoff + p) * B_ + b) * D_ + d] = mx;
    if (d == 0) {
        int any = 0;
        for (int l = l0; l < lend; l++) any |= vmask[b * L_ + l];
        kmask[(posoff + p) * B_ + b] = !any;   // 1 = ignore
    }
}

// ======================= fp32 GEMM: C = A(MxK) @ W(NxK)^T + bias =
// block 64x64, BK=16, 256 threads, 4x4 microtile
__global__ void gemm_kernel(const float* __restrict__ A, const float* __restrict__ W,
                            const float* __restrict__ bias, float* __restrict__ C,
                            int M, int N, int K, int doRelu, int doAcc)
{
    __shared__ float As[16][64];
    __shared__ float Ws[16][64];
    int bm = blockIdx.x * 64;
    int bn = blockIdx.y * 64;
    int t = threadIdx.x;
    int tx = t & 15, ty = t >> 4;
    int lm = t >> 2;
    int lk = (t & 3) * 4;
    float c[4][4] = {{0.f}};
    const float* Ab = A + (size_t)(bm + lm) * K + lk;
    const float* Wb = W + (size_t)(bn + lm) * K + lk;
    bool arow = (bm + lm) < M;
    for (int k0 = 0; k0 < K; k0 += 16) {
        float4 av = arow ? *(const float4*)(Ab + k0) : make_float4(0.f,0.f,0.f,0.f);
        float4 wv = *(const float4*)(Wb + k0);
        As[lk][lm] = av.x; As[lk+1][lm] = av.y; As[lk+2][lm] = av.z; As[lk+3][lm] = av.w;
        Ws[lk][lm] = wv.x; Ws[lk+1][lm] = wv.y; Ws[lk+2][lm] = wv.z; Ws[lk+3][lm] = wv.w;
        __syncthreads();
        #pragma unroll
        for (int kk = 0; kk < 16; kk++) {
            float4 a = *(const float4*)&As[kk][ty * 4];
            float4 bV = *(const float4*)&Ws[kk][tx * 4];
            c[0][0] += a.x * bV.x; c[0][1] += a.x * bV.y; c[0][2] += a.x * bV.z; c[0][3] += a.x * bV.w;
            c[1][0] += a.y * bV.x; c[1][1] += a.y * bV.y; c[1][2] += a.y * bV.z; c[1][3] += a.y * bV.w;
            c[2][0] += a.z * bV.x; c[2][1] += a.z * bV.y; c[2][2] += a.z * bV.z; c[2][3] += a.z * bV.w;
            c[3][0] += a.w * bV.x; c[3][1] += a.w * bV.y; c[3][2] += a.w * bV.z; c[3][3] += a.w * bV.w;
        }
        __syncthreads();
    }
    #pragma unroll
    for (int i = 0; i < 4; i++) {
        int row = bm + ty * 4 + i;
        if (row >= M) continue;
        #pragma unroll
        for (int j = 0; j < 4; j++) {
            int col = bn + tx * 4 + j;
            float v = c[i][j] + bias[col];
            if (doRelu) v = fmaxf(v, 0.f);
            float* p = C + (size_t)row * N + col;
            if (doAcc) *p += v; else *p = v;
        }
    }
}

// ======================= fused attention (flash style) ==========
// Q rows: (l*B+b), head h at cols h*64. QT=32, KT=32, 256 threads.
__global__ void attn_kernel(const float* __restrict__ Q, int ldq,
                            const float* __restrict__ K, int ldk,
                            const float* __restrict__ V, int ldv,
                            const int* __restrict__ mask, int msj, int msb,
                            float* __restrict__ O, int ldo,
                            int Lk, float scale)
{
    __shared__ float qs[32][65];
    __shared__ float ks[32][65];
    __shared__ float vs[32][65];
    __shared__ float ss[32][33];

    int b = blockIdx.y & 7;
    int h = blockIdx.y >> 3;
    int q0 = blockIdx.x * 32;
    int t = threadIdx.x;     // 256
    int r = t >> 3;          // 0..31 query row within tile
    int c8 = t & 7;

    // load Q tile (32x64)
    #pragma unroll
    for (int it = 0; it < 2; it++) {
        int id = t + it * 256;        // 0..511 float4s
        int rr = id >> 4;
        int cc = (id & 15) * 4;
        float4 xq = *(const float4*)(Q + ((size_t)(q0 + rr) * B_ + b) * ldq + h * HD_ + cc);
        qs[rr][cc] = xq.x; qs[rr][cc+1] = xq.y; qs[rr][cc+2] = xq.z; qs[rr][cc+3] = xq.w;
    }

    float o[8];
    #pragma unroll
    for (int i = 0; i < 8; i++) o[i] = 0.f;
    float m = -3.0e38f, l = 0.f;

    int ntile = (Lk + 31) / 32;
    for (int kt = 0; kt < ntile; kt++) {
        int j0 = kt * 32;
        __syncthreads();
        // load K,V tiles (each 32x64)
        #pragma unroll
        for (int it = 0; it < 2; it++) {
            int id = t + it * 256;
            int rr = id >> 4;
            int cc = (id & 15) * 4;
            int j = j0 + rr;
            float4 kv = make_float4(0.f,0.f,0.f,0.f), vv = make_float4(0.f,0.f,0.f,0.f);
            if (j < Lk) {
                kv = *(const float4*)(K + ((size_t)j * B_ + b) * ldk + h * HD_ + cc);
                vv = *(const float4*)(V + ((size_t)j * B_ + b) * ldv + h * HD_ + cc);
            }
            ks[rr][cc] = kv.x; ks[rr][cc+1] = kv.y; ks[rr][cc+2] = kv.z; ks[rr][cc+3] = kv.w;
            vs[rr][cc] = vv.x; vs[rr][cc+1] = vv.y; vs[rr][cc+2] = vv.z; vs[rr][cc+3] = vv.w;
        }
        __syncthreads();
        // scores: each thread computes 4 keys: jj = c8 + 8u
        float sc[4] = {0.f, 0.f, 0.f, 0.f};
        #pragma unroll 16
        for (int d = 0; d < HD_; d++) {
            float qd = qs[r][d];
            #pragma unroll
            for (int u = 0; u < 4; u++) sc[u] += qd * ks[c8 + 8*u][d];
        }
        float tmax = -3.0e38f;
        #pragma unroll
        for (int u = 0; u < 4; u++) {
            int j = j0 + c8 + 8*u;
            float val;
            if (j < Lk && mask[(size_t)j * msj + (size_t)b * msb] == 0)
                val = sc[u] * scale;
            else
                val = -3.0e38f;
            sc[u] = val;
            tmax = fmaxf(tmax, val);
        }
        #pragma unroll
        for (int off = 4; off > 0; off >>= 1)
            tmax = fmaxf(tmax, __shfl_xor_sync(0xffffffffu, tmax, off));
        float mn = fmaxf(m, tmax);
        float psum = 0.f;
        #pragma unroll
        for (int u = 0; u < 4; u++) {
            float p = (sc[u] <= -1e37f) ? 0.f : __expf(sc[u] - mn);
            ss[r][c8 + 8*u] = p;
            psum += p;
        }
        #pragma unroll
        for (int off = 4; off > 0; off >>= 1)
            psum += __shfl_xor_sync(0xffffffffu, psum, off);
        float factor = (mn <= -1e37f) ? 1.f : __expf(m - mn);
        m = mn;
        l = l * factor + psum;
        #pragma unroll
        for (int i = 0; i < 8; i++) o[i] *= factor;
        __syncwarp();
        #pragma unroll 8
        for (int j = 0; j < 32; j++) {
            float p = ss[r][j];
            #pragma unroll
            for (int i = 0; i < 8; i++)
                o[i] += p * vs[j][c8 + 8*i];
        }
    }
    float inv = 1.0f / l;
    #pragma unroll
    for (int i = 0; i < 8; i++) {
        int d = c8 + 8*i;
        O[((size_t)(q0 + r) * B_ + b) * ldo + h * HD_ + d] = o[i] * inv;
    }
}

// ======================= layer norm on (a+b) ====================
__device__ __forceinline__ float blockReduceSum256(float v)
{
    __shared__ float sh[8];
    int lane = threadIdx.x & 31, w = threadIdx.x >> 5;
    #pragma unroll
    for (int o = 16; o; o >>= 1) v += __shfl_xor_sync(0xffffffffu, v, o);
    if (lane == 0) sh[w] = v;
    __syncthreads();
    float r = (threadIdx.x < 8) ? sh[threadIdx.x] : 0.f;
    if (w == 0) {
        #pragma unroll
        for (int o = 4; o; o >>= 1) r += __shfl_xor_sync(0xffffffffu, r, o);
        if (lane == 0) sh[0] = r;
    }
    __syncthreads();
    r = sh[0];
    __syncthreads();
    return r;
}

__global__ void ln_add_kernel(const float* __restrict__ a, const float* __restrict__ b,
                              const float* __restrict__ g, const float* __restrict__ bet,
                              float* __restrict__ out)
{
    int row = blockIdx.x, t = threadIdx.x;   // 256 threads, row of 512
    const float* ap = a + (size_t)row * D_;
    const float* bp = b + (size_t)row * D_;
    float v0 = ap[t] + bp[t];
    float v1 = ap[t + 256] + bp[t + 256];
    float mu = blockReduceSum256(v0 + v1) * (1.f / D_);
    float d0 = v0 - mu, d1 = v1 - mu;
    float var = blockReduceSum256(d0 * d0 + d1 * d1) * (1.f / D_);
    float rs = rsqrtf(var + 1e-5f);
    float* op = out + (size_t)row * D_;
    op[t] = d0 * rs * g[t] + bet[t];
    op[t + 256] = d1 * rs * g[t + 256] + bet[t + 256];
}

__global__ void add_kernel(const float* __restrict__ a, const float* __restrict__ b,
                           float* __restrict__ c, int n)
{
    int i = blockIdx.x * blockDim.x + threadIdx.x;
    if (i < n) c[i] = a[i] + b[i];
}

// ======================= host orchestration =====================
extern "C" void kernel_launch(void* const* d_in, const int* in_sizes, int n_in,
                              void* d_out, int out_size)
{
    const float* x        = (const float*)d_in[0];
    const float* txt      = (const float*)d_in[1];
    const unsigned char* vmask_raw = (const unsigned char*)d_in[2];
    const unsigned char* tmask_raw = (const unsigned char*)d_in[3];
    const float* wts_w    = (const float*)d_in[4];
    const float* wts_b    = (const float*)d_in[5];
    const float* ec_in_w  = (const float*)d_in[6];
    const float* ec_in_b  = (const float*)d_in[7];
    const float* ec_out_w = (const float*)d_in[8];
    const float* ec_out_b = (const float*)d_in[9];
    const float* cc_in_w  = (const float*)d_in[10];
    const float* cc_in_b  = (const float*)d_in[11];
    const float* cc_out_w = (const float*)d_in[12];
    const float* cc_out_b = (const float*)d_in[13];
    const float* ec_ng    = (const float*)d_in[14];
    const float* ec_nb    = (const float*)d_in[15];
    const float* cc_ng    = (const float*)d_in[16];
    const float* cc_nb    = (const float*)d_in[17];
    const float* fu_ng    = (const float*)d_in[18];
    const float* fu_nb    = (const float*)d_in[19];
    const float* lin1_w   = (const float*)d_in[20];
    const float* lin1_b   = (const float*)d_in[21];
    const float* lin2_w   = (const float*)d_in[22];
    const float* lin2_b   = (const float*)d_in[23];
    float* out = (float*)d_out;

    float *sent, *scores, *keys, *qkv, *q, *k, *v, *attn, *tmp, *xec, *total, *xcc, *sum, *h1;
    int *vmask, *tmask, *ecmask, *kmask;
    cudaGetSymbolAddress((void**)&sent,   g_sent);
    cudaGetSymbolAddress((void**)&scores, g_scores);
    cudaGetSymbolAddress((void**)&vmask,  g_vmask);
    cudaGetSymbolAddress((void**)&tmask,  g_tmask);
    cudaGetSymbolAddress((void**)&ecmask, g_ecmask);
    cudaGetSymbolAddress((void**)&kmask,  g_kmask);
    cudaGetSymbolAddress((void**)&keys,   g_keys);
    cudaGetSymbolAddress((void**)&qkv,    g_qkv);
    cudaGetSymbolAddress((void**)&q,      g_q);
    cudaGetSymbolAddress((void**)&k,      g_k);
    cudaGetSymbolAddress((void**)&v,      g_v);
    cudaGetSymbolAddress((void**)&attn,   g_attn);
    cudaGetSymbolAddress((void**)&tmp,    g_tmp);
    cudaGetSymbolAddress((void**)&xec,    g_xec);
    cudaGetSymbolAddress((void**)&total,  g_total);
    cudaGetSymbolAddress((void**)&xcc,    g_xcc);
    cudaGetSymbolAddress((void**)&sum,    g_sum);
    cudaGetSymbolAddress((void**)&h1,     g_h1);

    const int MROWS = L_ * B_;   // 8192
    const float SCALE = 0.125f;  // 1/sqrt(64)

    // masks
    mask_convert_kernel<<<(B_*L_ + 255)/256, 256>>>(vmask_raw, vmask, B_*L_);
    mask_convert_kernel<<<1, 256>>>(tmask_raw, tmask, B_*LT_);

    // sentence pooling + relevance scores + top-k mask
    sent_kernel<<<B_, 512>>>(txt, tmask, wts_w, wts_b, sent);
    score_kernel<<<dim3(L_, B_), 128>>>(x, sent, vmask, scores);
    topk_kernel<<<B_, 512>>>(scores, ecmask);

    // pooled keys for all 8 strides
    const int S[8]   = {1, 2, 4, 8, 16, 24, 32, 48};
    const int LP[8]  = {1024, 512, 256, 128, 64, 43, 32, 22};
    const int OFF[8] = {0, 1024, 1536, 1792, 1920, 1984, 2027, 2059};
    for (int si = 0; si < 8; si++)
        pool_kernel<<<dim3(LP[si], B_), 512>>>(x, vmask, keys, kmask, S[si], OFF[si]);

    // ===== essential-context self attention =====
    gemm_kernel<<<dim3(MROWS/64, 1536/64), 256>>>(x, ec_in_w, ec_in_b, qkv,
                                                  MROWS, 1536, D_, 0, 0);
    attn_kernel<<<dim3(L_/32, B_*H_), 256>>>(qkv, 1536, qkv + 512, 1536, qkv + 1024, 1536,
                                             ecmask, 1, L_, attn, D_, L_, SCALE);
    gemm_kernel<<<dim3(MROWS/64, D_/64), 256>>>(attn, ec_out_w, ec_out_b, tmp,
                                                MROWS, D_, D_, 0, 0);
    ln_add_kernel<<<MROWS, 256>>>(x, tmp, ec_ng, ec_nb, xec);

    // ===== multi-stride cross-context attentions =====
    const int GO[4] = {0, 1536, 1920, 2027};
    const int LK[4] = {1536, 384, 107, 54};
    for (int i = 0; i < 4; i++) {
        const float* Wq = cc_in_w + (size_t)i * 3 * D_ * D_;
        const float* Wk = Wq + (size_t)D_ * D_;
        const float* Wv = Wk + (size_t)D_ * D_;
        const float* bq = cc_in_b + (size_t)i * 3 * D_;
        const float* bk = bq + D_;
        const float* bv = bk + D_;
        int mk = LK[i] * B_;
        gemm_kernel<<<dim3(MROWS/64, D_/64), 256>>>(x, Wq, bq, q, MROWS, D_, D_, 0, 0);
        gemm_kernel<<<dim3((mk + 63)/64, D_/64), 256>>>(keys + (size_t)GO[i]*B_*D_, Wk, bk, k,
                                                        mk, D_, D_, 0, 0);
        gemm_kernel<<<dim3((mk + 63)/64, D_/64), 256>>>(keys + (size_t)GO[i]*B_*D_, Wv, bv, v,
                                                        mk, D_, D_, 0, 0);
        attn_kernel<<<dim3(L_/32, B_*H_), 256>>>(q, D_, k, D_, v, D_,
                                                 kmask + GO[i]*B_, B_, 1,
                                                 attn, D_, LK[i], SCALE);
        gemm_kernel<<<dim3(MROWS/64, D_/64), 256>>>(attn, cc_out_w + (size_t)i*D_*D_,
                                                    cc_out_b + (size_t)i*D_, total,
                                                    MROWS, D_, D_, 0, (i > 0) ? 1 : 0);
    }
    ln_add_kernel<<<MROWS, 256>>>(x, total, cc_ng, cc_nb, xcc);

    // ===== fusion FFN =====
    add_kernel<<<(MROWS*D_ + 255)/256, 256>>>(xec, xcc, sum, MROWS*D_);
    gemm_kernel<<<dim3(MROWS/64, 2048/64), 256>>>(sum, lin1_w, lin1_b, h1,
                                                  MROWS, 2048, D_, 1, 0);
    gemm_kernel<<<dim3(MROWS/64, D_/64), 256>>>(h1, lin2_w, lin2_b, tmp,
                                                MROWS, D_, 2048, 0, 0);
    ln_add_kernel<<<MROWS, 256>>>(sum, tmp, fu_ng, fu_nb, out);
}

// round 13
// speedup vs baseline: 3.0797x; 3.0797x over previous
#include <cuda_runtime.h>
#include <cuda_bf16.h>
#include <math.h>

// ======================= problem constants =======================
#define L_  1024
#define B_  8
#define D_  512
#define LT_ 32
#define H_  8
#define HD_ 64
#define TOTPOS 2081   // 1024+512+256+128+64+43+32+22

// ======================= scratch (static device memory) =========
__device__ float g_sent[B_*D_];
__device__ float g_scores[B_*L_];
__device__ int   g_vmask[B_*L_];
__device__ int   g_tmask[B_*LT_];
__device__ int   g_ecmask[B_*L_];
__device__ int   g_kmask[TOTPOS*B_];
__device__ float g_keys[TOTPOS*B_*D_];
__device__ float g_qkv[8192*1536];     // also reused as cc KV buffer (12288*1024)
__device__ float g_q[8192*512];
__device__ float g_attn[8192*512];
__device__ float g_tmp[8192*512];
__device__ float g_xec[8192*512];
__device__ float g_total[8192*512];
__device__ float g_xcc[8192*512];
__device__ float g_sum[8192*512];
__device__ float g_h1[8192*2048];

// ======================= mask dtype conversion ==================
__global__ void mask_convert_kernel(const unsigned char* __restrict__ raw,
                                    int* __restrict__ out, int n)
{
    int i = blockIdx.x * blockDim.x + threadIdx.x;
    if (i >= n) return;
    int v;
    if (raw[1] == 1) {                // 1-byte bool
        v = raw[i] != 0;
    } else if (raw[0] == 1) {         // int32
        v = ((const int*)raw)[i] != 0;
    } else {                          // float32
        v = ((const float*)raw)[i] != 0.0f;
    }
    out[i] = v;
}

// ======================= sentence pooling =======================
__global__ void sent_kernel(const float* __restrict__ txt, const int* __restrict__ tmask,
                            const float* __restrict__ wts_w, const float* __restrict__ wts_b,
                            float* __restrict__ sent)
{
    __shared__ float aw[LT_];
    int b = blockIdx.x;
    int t = threadIdx.x;            // 512 threads
    int warp = t >> 5, lane = t & 31;
    for (int tok = warp; tok < LT_; tok += 16) {
        float s = 0.f;
        for (int d = lane; d < D_; d += 32)
            s += txt[((size_t)tok * B_ + b) * D_ + d] * wts_w[d];
        #pragma unroll
        for (int off = 16; off; off >>= 1) s += __shfl_xor_sync(0xffffffffu, s, off);
        if (lane == 0) {
            s += wts_b[0];
            if (!tmask[b * LT_ + tok]) s = -1e9f;
            aw[tok] = s;
        }
    }
    __syncthreads();
    if (t == 0) {
        float mx = -3e38f;
        for (int i = 0; i < LT_; i++) mx = fmaxf(mx, aw[i]);
        float sum = 0.f;
        for (int i = 0; i < LT_; i++) { aw[i] = __expf(aw[i] - mx); sum += aw[i]; }
        float inv = 1.f / sum;
        for (int i = 0; i < LT_; i++) aw[i] *= inv;
    }
    __syncthreads();
    float s = 0.f;
    for (int tok = 0; tok < LT_; tok++)
        s += aw[tok] * txt[((size_t)tok * B_ + b) * D_ + t];
    sent[b * D_ + t] = s;
}

// ======================= relevance scores =======================
__global__ void score_kernel(const float* __restrict__ x, const float* __restrict__ sent,
                             const int* __restrict__ vmask, float* __restrict__ scores)
{
    int l = blockIdx.x, b = blockIdx.y;
    int t = threadIdx.x;            // 128
    __shared__ float r4[4];
    float s = 0.f;
    for (int d = t; d < D_; d += 128)
        s += x[((size_t)l * B_ + b) * D_ + d] * sent[b * D_ + d];
    #pragma unroll
    for (int off = 16; off; off >>= 1) s += __shfl_xor_sync(0xffffffffu, s, off);
    if ((t & 31) == 0) r4[t >> 5] = s;
    __syncthreads();
    if (t == 0) {
        s = r4[0] + r4[1] + r4[2] + r4[3];
        scores[b * L_ + l] = vmask[b * L_ + l] ? s : -1e9f;
    }
}

// ======================= top-k (k=512) via bitonic sort =========
__global__ void topk_kernel(const float* __restrict__ scores, int* __restrict__ ecmask)
{
    __shared__ float sv[L_];
    __shared__ int cnt;
    int b = blockIdx.x, t = threadIdx.x;   // 512 threads
    sv[t] = scores[b * L_ + t];
    sv[t + 512] = scores[b * L_ + t + 512];
    if (t == 0) cnt = 0;
    __syncthreads();
    for (int k = 2; k <= L_; k <<= 1) {
        for (int j = k >> 1; j > 0; j >>= 1) {
            for (int i = t; i < L_; i += 512) {
                int ixj = i ^ j;
                if (ixj > i) {
                    bool up = ((i & k) == 0);
                    float a = sv[i], c = sv[ixj];
                    if ((a > c) == up) { sv[i] = c; sv[ixj] = a; }
                }
            }
            __syncthreads();
        }
    }
    float thr = sv[512];
    for (int i = t; i < L_; i += 512) {
        float sc = scores[b * L_ + i];
        int ig = 1;
        if (sc > thr) { ig = 0; atomicAdd(&cnt, 1); }
        ecmask[b * L_ + i] = ig;
    }
    __syncthreads();
    if (t == 0) {
        int need = 512 - cnt;
        for (int i = 0; i < L_ && need > 0; i++) {
            if (scores[b * L_ + i] == thr && ecmask[b * L_ + i]) {
                ecmask[b * L_ + i] = 0; need--;
            }
        }
    }
}

// ======================= max-pool keys ==========================
__global__ void pool_kernel(const float* __restrict__ x, const int* __restrict__ vmask,
                            float* __restrict__ keys, int* __restrict__ kmask,
                            int s, int posoff)
{
    int p = blockIdx.x, b = blockIdx.y, d = threadIdx.x;  // 512 threads
    int l0 = p * s;
    float mx = (l0 + s > L_) ? 0.0f : -3.0e38f;  // zero-pad participates in max
    int lend = l0 + s; if (lend > L_) lend = L_;
    for (int l = l0; l < lend; l++)
        mx = fmaxf(mx, x[((size_t)l * B_ + b) * D_ + d]);
    keys[((size_t)(posoff + p) * B_ + b) * D_ + d] = mx;
    if (d == 0) {
        int any = 0;
        for (int l = l0; l < lend; l++) any |= vmask[b * L_ + l];
        kmask[(posoff + p) * B_ + b] = !any;   // 1 = ignore
    }
}

// ======================= tf32 helpers ===========================
__device__ __forceinline__ unsigned f2tf(float f)
{
    unsigned u;
    asm("cvt.rna.tf32.f32 %0, %1;" : "=r"(u) : "f"(f));
    return u;
}

#define MMA_TF32(C, a0, a1, a2, a3, b0, b1)                                  \
    asm volatile(                                                            \
        "mma.sync.aligned.m16n8k8.row.col.f32.tf32.tf32.f32 "                \
        "{%0,%1,%2,%3}, {%4,%5,%6,%7}, {%8,%9}, {%0,%1,%2,%3};"              \
        : "+f"((C)[0]), "+f"((C)[1]), "+f"((C)[2]), "+f"((C)[3])             \
        : "r"(a0), "r"(a1), "r"(a2), "r"(a3), "r"(b0), "r"(b1))

// ======================= tf32 GEMM: C = A(MxK) @ W(NxK)^T + bias =
// block 128x128, BK=16, 256 threads (8 warps in 2x4), mma.m16n8k8.tf32
__global__ __launch_bounds__(256, 2)
void gemm_tf32_kernel(const float* __restrict__ A, const float* __restrict__ W,
                      const float* __restrict__ bias, float* __restrict__ C,
                      int M, int N, int K, int doRelu, int doAcc)
{
    __shared__ unsigned As[16][132];   // [k][m]
    __shared__ unsigned Bs[16][132];   // [k][n]
    int bm = blockIdx.x * 128;
    int bn = blockIdx.y * 128;
    int tid = threadIdx.x;
    int wid = tid >> 5, lane = tid & 31;
    int g = lane >> 2, tig = lane & 3;
    int wm = (wid & 1) * 64;
    int wn = (wid >> 1) * 32;

    float c[4][4][4];
    #pragma unroll
    for (int mi = 0; mi < 4; mi++)
        #pragma unroll
        for (int ni = 0; ni < 4; ni++)
            #pragma unroll
            for (int r = 0; r < 4; r++) c[mi][ni][r] = 0.f;

    int lrow = tid >> 2;          // 0..63
    int lcol = (tid & 3) * 4;     // 0,4,8,12

    for (int k0 = 0; k0 < K; k0 += 16) {
        #pragma unroll
        for (int h = 0; h < 2; h++) {
            int r = lrow + h * 64;
            float4 av = make_float4(0.f, 0.f, 0.f, 0.f);
            if (bm + r < M)
                av = *(const float4*)(A + (size_t)(bm + r) * K + k0 + lcol);
            As[lcol][r]   = f2tf(av.x);
            As[lcol+1][r] = f2tf(av.y);
            As[lcol+2][r] = f2tf(av.z);
            As[lcol+3][r] = f2tf(av.w);
            float4 wv = *(const float4*)(W + (size_t)(bn + r) * K + k0 + lcol);
            Bs[lcol][r]   = f2tf(wv.x);
            Bs[lcol+1][r] = f2tf(wv.y);
            Bs[lcol+2][r] = f2tf(wv.z);
            Bs[lcol+3][r] = f2tf(wv.w);
        }
        __syncthreads();
        #pragma unroll
        for (int kk = 0; kk < 16; kk += 8) {
            unsigned bf[4][2];
            #pragma unroll
            for (int ni = 0; ni < 4; ni++) {
                int n = wn + ni * 8 + g;
                bf[ni][0] = Bs[kk + tig][n];
                bf[ni][1] = Bs[kk + tig + 4][n];
            }
            #pragma unroll
            for (int mi = 0; mi < 4; mi++) {
                int m = wm + mi * 16 + g;
                unsigned a0 = As[kk + tig][m];
                unsigned a1 = As[kk + tig][m + 8];
                unsigned a2 = As[kk + tig + 4][m];
                unsigned a3 = As[kk + tig + 4][m + 8];
                #pragma unroll
                for (int ni = 0; ni < 4; ni++)
                    MMA_TF32(c[mi][ni], a0, a1, a2, a3, bf[ni][0], bf[ni][1]);
            }
        }
        __syncthreads();
    }

    #pragma unroll
    for (int mi = 0; mi < 4; mi++) {
        #pragma unroll
        for (int ni = 0; ni < 4; ni++) {
            int col = bn + wn + ni * 8 + tig * 2;
            float b0 = bias[col], b1 = bias[col + 1];
            #pragma unroll
            for (int h = 0; h < 2; h++) {
                int row = bm + wm + mi * 16 + g + h * 8;
                if (row >= M) continue;
                float v0 = c[mi][ni][h * 2]     + b0;
                float v1 = c[mi][ni][h * 2 + 1] + b1;
                if (doRelu) { v0 = fmaxf(v0, 0.f); v1 = fmaxf(v1, 0.f); }
                float* p = C + (size_t)row * N + col;
                if (doAcc) { p[0] += v0; p[1] += v1; }
                else       { p[0] = v0;  p[1] = v1;  }
            }
        }
    }
}

// ======================= MMA flash attention ====================
// grid (L/64, B*H), 128 threads = 4 warps, each warp 16 q rows.
// S = Q K^T and O += P V via mma.m16n8k8.tf32.  K-tile = 64 keys.
// P is staged through the (dead) K smem buffer to convert C->A layout.
__global__ __launch_bounds__(128)
void attn_mma_kernel(const float* __restrict__ Q, int ldq,
                     const float* __restrict__ K, int ldk,
                     const float* __restrict__ V, int ldv,
                     const int* __restrict__ mask, int msj, int msb,
                     float* __restrict__ O, int ldo,
                     int Lk, float scale)
{
    __shared__ float ks[64][68];
    __shared__ float vs[64][68];
    __shared__ int   msk[64];

    int b = blockIdx.y & 7;
    int h = blockIdx.y >> 3;
    int q0 = blockIdx.x * 64;
    int tid = threadIdx.x;
    int w = tid >> 5, lane = tid & 31;
    int g = lane >> 2, tig = lane & 3;
    int r0 = w * 16 + g;      // local q row (first)
    int r1 = r0 + 8;          // local q row (second)

    // Q fragments, register-resident for whole kernel
    unsigned qf[8][4];
    {
        const float* q0p = Q + ((size_t)(q0 + r0) * B_ + b) * ldq + h * HD_;
        const float* q1p = Q + ((size_t)(q0 + r1) * B_ + b) * ldq + h * HD_;
        #pragma unroll
        for (int kc = 0; kc < 8; kc++) {
            qf[kc][0] = f2tf(q0p[kc * 8 + tig]);
            qf[kc][1] = f2tf(q1p[kc * 8 + tig]);
            qf[kc][2] = f2tf(q0p[kc * 8 + tig + 4]);
            qf[kc][3] = f2tf(q1p[kc * 8 + tig + 4]);
        }
    }

    float oacc[8][4];
    #pragma unroll
    for (int ni = 0; ni < 8; ni++)
        #pragma unroll
        for (int r = 0; r < 4; r++) oacc[ni][r] = 0.f;
    float m0 = -3.0e38f, m1 = -3.0e38f, l0s = 0.f, l1s = 0.f;

    for (int j0 = 0; j0 < Lk; j0 += 64) {
        // load K,V tile (zero-filled out of range) + mask
        #pragma unroll
        for (int it = 0; it < 8; it++) {
            int id = tid + it * 128;       // 0..1023 float4 slots
            int row = id >> 4, c4 = (id & 15) * 4;
            int j = j0 + row;
            float4 kv = make_float4(0.f,0.f,0.f,0.f), vv = make_float4(0.f,0.f,0.f,0.f);
            if (j < Lk) {
                kv = *(const float4*)(K + ((size_t)j * B_ + b) * ldk + h * HD_ + c4);
                vv = *(const float4*)(V + ((size_t)j * B_ + b) * ldv + h * HD_ + c4);
            }
            *(float4*)&ks[row][c4] = kv;
            *(float4*)&vs[row][c4] = vv;
        }
        if (tid < 64)
            msk[tid] = (j0 + tid < Lk) ? mask[(size_t)(j0 + tid) * msj + (size_t)b * msb] : 1;
        __syncthreads();

        // S = Q K^T  (A = Q regs, B = K from smem)
        float s[8][4];
        #pragma unroll
        for (int ni = 0; ni < 8; ni++)
            #pragma unroll
            for (int r = 0; r < 4; r++) s[ni][r] = 0.f;
        #pragma unroll
        for (int kc = 0; kc < 8; kc++) {
            #pragma unroll
            for (int ni = 0; ni < 8; ni++) {
                unsigned b0 = f2tf(ks[ni * 8 + g][kc * 8 + tig]);
                unsigned b1 = f2tf(ks[ni * 8 + g][kc * 8 + tig + 4]);
                MMA_TF32(s[ni], qf[kc][0], qf[kc][1], qf[kc][2], qf[kc][3], b0, b1);
            }
        }
        __syncthreads();   // all warps finished reading ks; it becomes the P buffer

        // mask + scale + online softmax (C layout: rows r0/r1, cols ni*8+2tig{,+1})
        float tm0 = -3.0e38f, tm1 = -3.0e38f;
        #pragma unroll
        for (int ni = 0; ni < 8; ni++) {
            int ja = ni * 8 + 2 * tig;
            bool ia = msk[ja] != 0;
            bool ib = msk[ja + 1] != 0;
            s[ni][0] = ia ? -3.0e38f : s[ni][0] * scale;
            s[ni][1] = ib ? -3.0e38f : s[ni][1] * scale;
            s[ni][2] = ia ? -3.0e38f : s[ni][2] * scale;
            s[ni][3] = ib ? -3.0e38f : s[ni][3] * scale;
            tm0 = fmaxf(tm0, fmaxf(s[ni][0], s[ni][1]));
            tm1 = fmaxf(tm1, fmaxf(s[ni][2], s[ni][3]));
        }
        tm0 = fmaxf(tm0, __shfl_xor_sync(0xffffffffu, tm0, 1));
        tm0 = fmaxf(tm0, __shfl_xor_sync(0xffffffffu, tm0, 2));
        tm1 = fmaxf(tm1, __shfl_xor_sync(0xffffffffu, tm1, 1));
        tm1 = fmaxf(tm1, __shfl_xor_sync(0xffffffffu, tm1, 2));
        float mn0 = fmaxf(m0, tm0), mn1 = fmaxf(m1, tm1);
        float ps0 = 0.f, ps1 = 0.f;
        #pragma unroll
        for (int ni = 0; ni < 8; ni++) {
            s[ni][0] = (s[ni][0] <= -1e37f) ? 0.f : __expf(s[ni][0] - mn0);
            s[ni][1] = (s[ni][1] <= -1e37f) ? 0.f : __expf(s[ni][1] - mn0);
            s[ni][2] = (s[ni][2] <= -1e37f) ? 0.f : __expf(s[ni][2] - mn1);
            s[ni][3] = (s[ni][3] <= -1e37f) ? 0.f : __expf(s[ni][3] - mn1);
            ps0 += s[ni][0] + s[ni][1];
            ps1 += s[ni][2] + s[ni][3];
        }
        ps0 += __shfl_xor_sync(0xffffffffu, ps0, 1);
        ps0 += __shfl_xor_sync(0xffffffffu, ps0, 2);
        ps1 += __shfl_xor_sync(0xffffffffu, ps1, 1);
        ps1 += __shfl_xor_sync(0xffffffffu, ps1, 2);
        float f0 = (mn0 <= -1e37f) ? 1.f : __expf(m0 - mn0);
        float f1 = (mn1 <= -1e37f) ? 1.f : __expf(m1 - mn1);
        m0 = mn0; m1 = mn1;
        l0s = l0s * f0 + ps0;
        l1s = l1s * f1 + ps1;

        // stage P into ks (warp-local rows), rescale O
        #pragma unroll
        for (int ni = 0; ni < 8; ni++) {
            ks[r0][ni * 8 + 2 * tig]     = s[ni][0];
            ks[r0][ni * 8 + 2 * tig + 1] = s[ni][1];
            ks[r1][ni * 8 + 2 * tig]     = s[ni][2];
            ks[r1][ni * 8 + 2 * tig + 1] = s[ni][3];
            oacc[ni][0] *= f0; oacc[ni][1] *= f0;
            oacc[ni][2] *= f1; oacc[ni][3] *= f1;
        }
        __syncwarp();

        // O += P V  (A = P from smem, B = V from smem)
        #pragma unroll
        for (int kc = 0; kc < 8; kc++) {
            unsigned pa0 = f2tf(ks[r0][kc * 8 + tig]);
            unsigned pa1 = f2tf(ks[r1][kc * 8 + tig]);
            unsigned pa2 = f2tf(ks[r0][kc * 8 + tig + 4]);
            unsigned pa3 = f2tf(ks[r1][kc * 8 + tig + 4]);
            #pragma unroll
            for (int ni = 0; ni < 8; ni++) {
                unsigned vb0 = f2tf(vs[kc * 8 + tig][ni * 8 + g]);
                unsigned vb1 = f2tf(vs[kc * 8 + tig + 4][ni * 8 + g]);
                MMA_TF32(oacc[ni], pa0, pa1, pa2, pa3, vb0, vb1);
            }
        }
        __syncthreads();   // done with ks(P)/vs before next tile load
    }

    float i0 = 1.0f / l0s, i1 = 1.0f / l1s;
    #pragma unroll
    for (int ni = 0; ni < 8; ni++) {
        int col = h * HD_ + ni * 8 + 2 * tig;
        float* p0 = O + ((size_t)(q0 + r0) * B_ + b) * ldo + col;
        p0[0] = oacc[ni][0] * i0; p0[1] = oacc[ni][1] * i0;
        float* p1 = O + ((size_t)(q0 + r1) * B_ + b) * ldo + col;
        p1[0] = oacc[ni][2] * i1; p1[1] = oacc[ni][3] * i1;
    }
}

// ======================= layer norm on (a+b) ====================
__device__ __forceinline__ float blockReduceSum256(float v)
{
    __shared__ float sh[8];
    int lane = threadIdx.x & 31, w = threadIdx.x >> 5;
    #pragma unroll
    for (int o = 16; o; o >>= 1) v += __shfl_xor_sync(0xffffffffu, v, o);
    if (lane == 0) sh[w] = v;
    __syncthreads();
    float r = (threadIdx.x < 8) ? sh[threadIdx.x] : 0.f;
    if (w == 0) {
        #pragma unroll
        for (int o = 4; o; o >>= 1) r += __shfl_xor_sync(0xffffffffu, r, o);
        if (lane == 0) sh[0] = r;
    }
    __syncthreads();
    r = sh[0];
    __syncthreads();
    return r;
}

__global__ void ln_add_kernel(const float* __restrict__ a, const float* __restrict__ b,
                              const float* __restrict__ g, const float* __restrict__ bet,
                              float* __restrict__ out)
{
    int row = blockIdx.x, t = threadIdx.x;
    const float* ap = a + (size_t)row * D_;
    const float* bp = b + (size_t)row * D_;
    float v0 = ap[t] + bp[t];
    float v1 = ap[t + 256] + bp[t + 256];
    float mu = blockReduceSum256(v0 + v1) * (1.f / D_);
    float d0 = v0 - mu, d1 = v1 - mu;
    float var = blockReduceSum256(d0 * d0 + d1 * d1) * (1.f / D_);
    float rs = rsqrtf(var + 1e-5f);
    float* op = out + (size_t)row * D_;
    op[t] = d0 * rs * g[t] + bet[t];
    op[t + 256] = d1 * rs * g[t + 256] + bet[t + 256];
}

__global__ void add_kernel(const float* __restrict__ a, const float* __restrict__ b,
                           float* __restrict__ c, int n)
{
    int i = blockIdx.x * blockDim.x + threadIdx.x;
    if (i < n) c[i] = a[i] + b[i];
}

// ======================= host orchestration =====================
extern "C" void kernel_launch(void* const* d_in, const int* in_sizes, int n_in,
                              void* d_out, int out_size)
{
    const float* x        = (const float*)d_in[0];
    const float* txt      = (const float*)d_in[1];
    const unsigned char* vmask_raw = (const unsigned char*)d_in[2];
    const unsigned char* tmask_raw = (const unsigned char*)d_in[3];
    const float* wts_w    = (const float*)d_in[4];
    const float* wts_b    = (const float*)d_in[5];
    const float* ec_in_w  = (const float*)d_in[6];
    const float* ec_in_b  = (const float*)d_in[7];
    const float* ec_out_w = (const float*)d_in[8];
    const float* ec_out_b = (const float*)d_in[9];
    const float* cc_in_w  = (const float*)d_in[10];
    const float* cc_in_b  = (const float*)d_in[11];
    const float* cc_out_w = (const float*)d_in[12];
    const float* cc_out_b = (const float*)d_in[13];
    const float* ec_ng    = (const float*)d_in[14];
    const float* ec_nb    = (const float*)d_in[15];
    const float* cc_ng    = (const float*)d_in[16];
    const float* cc_nb    = (const float*)d_in[17];
    const float* fu_ng    = (const float*)d_in[18];
    const float* fu_nb    = (const float*)d_in[19];
    const float* lin1_w   = (const float*)d_in[20];
    const float* lin1_b   = (const float*)d_in[21];
    const float* lin2_w   = (const float*)d_in[22];
    const float* lin2_b   = (const float*)d_in[23];
    float* out = (float*)d_out;

    float *sent, *scores, *keys, *qkv, *q, *attn, *tmp, *xec, *total, *xcc, *sum, *h1;
    int *vmask, *tmask, *ecmask, *kmask;
    cudaGetSymbolAddress((void**)&sent,   g_sent);
    cudaGetSymbolAddress((void**)&scores, g_scores);
    cudaGetSymbolAddress((void**)&vmask,  g_vmask);
    cudaGetSymbolAddress((void**)&tmask,  g_tmask);
    cudaGetSymbolAddress((void**)&ecmask, g_ecmask);
    cudaGetSymbolAddress((void**)&kmask,  g_kmask);
    cudaGetSymbolAddress((void**)&keys,   g_keys);
    cudaGetSymbolAddress((void**)&qkv,    g_qkv);
    cudaGetSymbolAddress((void**)&q,      g_q);
    cudaGetSymbolAddress((void**)&attn,   g_attn);
    cudaGetSymbolAddress((void**)&tmp,    g_tmp);
    cudaGetSymbolAddress((void**)&xec,    g_xec);
    cudaGetSymbolAddress((void**)&total,  g_total);
    cudaGetSymbolAddress((void**)&xcc,    g_xcc);
    cudaGetSymbolAddress((void**)&sum,    g_sum);
    cudaGetSymbolAddress((void**)&h1,     g_h1);

    const int MROWS = L_ * B_;   // 8192
    const float SCALE = 0.125f;  // 1/sqrt(64)

    // masks
    mask_convert_kernel<<<(B_*L_ + 255)/256, 256>>>(vmask_raw, vmask, B_*L_);
    mask_convert_kernel<<<1, 256>>>(tmask_raw, tmask, B_*LT_);

    // sentence pooling + relevance scores + top-k mask
    sent_kernel<<<B_, 512>>>(txt, tmask, wts_w, wts_b, sent);
    score_kernel<<<dim3(L_, B_), 128>>>(x, sent, vmask, scores);
    topk_kernel<<<B_, 512>>>(scores, ecmask);

    // pooled keys for all 8 strides
    const int S[8]   = {1, 2, 4, 8, 16, 24, 32, 48};
    const int LP[8]  = {1024, 512, 256, 128, 64, 43, 32, 22};
    const int OFF[8] = {0, 1024, 1536, 1792, 1920, 1984, 2027, 2059};
    for (int si = 0; si < 8; si++)
        pool_kernel<<<dim3(LP[si], B_), 512>>>(x, vmask, keys, kmask, S[si], OFF[si]);

    // ===== essential-context self attention =====
    gemm_tf32_kernel<<<dim3(MROWS/128, 1536/128), 256>>>(x, ec_in_w, ec_in_b, qkv,
                                                         MROWS, 1536, D_, 0, 0);
    attn_mma_kernel<<<dim3(L_/64, B_*H_), 128>>>(qkv, 1536, qkv + 512, 1536, qkv + 1024, 1536,
                                                 ecmask, 1, L_, attn, D_, L_, SCALE);
    gemm_tf32_kernel<<<dim3(MROWS/128, D_/128), 256>>>(attn, ec_out_w, ec_out_b, tmp,
                                                       MROWS, D_, D_, 0, 0);
    ln_add_kernel<<<MROWS, 256>>>(x, tmp, ec_ng, ec_nb, xec);

    // ===== multi-stride cross-context attentions =====
    const int GO[4] = {0, 1536, 1920, 2027};
    const int LK[4] = {1536, 384, 107, 54};
    for (int i = 0; i < 4; i++) {
        const float* Wq = cc_in_w + (size_t)i * 3 * D_ * D_;
        const float* Wkv = Wq + (size_t)D_ * D_;           // K and V weights contiguous (1024 rows)
        const float* bq  = cc_in_b + (size_t)i * 3 * D_;
        const float* bkv = bq + D_;                        // K and V biases contiguous
        int mk = LK[i] * B_;
        gemm_tf32_kernel<<<dim3(MROWS/128, D_/128), 256>>>(x, Wq, bq, q, MROWS, D_, D_, 0, 0);
        // fused K+V projection: out ld = 1024, k at col 0, v at col 512 (reuse qkv buffer)
        gemm_tf32_kernel<<<dim3((mk + 127)/128, 1024/128), 256>>>(
            keys + (size_t)GO[i]*B_*D_, Wkv, bkv, qkv, mk, 1024, D_, 0, 0);
        attn_mma_kernel<<<dim3(L_/64, B_*H_), 128>>>(q, D_, qkv, 1024, qkv + 512, 1024,
                                                     kmask + GO[i]*B_, B_, 1,
                                                     attn, D_, LK[i], SCALE);
        gemm_tf32_kernel<<<dim3(MROWS/128, D_/128), 256>>>(attn, cc_out_w + (size_t)i*D_*D_,
                                                           cc_out_b + (size_t)i*D_, total,
                                                           MROWS, D_, D_, 0, (i > 0) ? 1 : 0);
    }
    ln_add_kernel<<<MROWS, 256>>>(x, total, cc_ng, cc_nb, xcc);

    // ===== fusion FFN =====
    add_kernel<<<(MROWS*D_ + 255)/256, 256>>>(xec, xcc, sum, MROWS*D_);
    gemm_tf32_kernel<<<dim3(MROWS/128, 2048/128), 256>>>(sum, lin1_w, lin1_b, h1,
                                                         MROWS, 2048, D_, 1, 0);
    gemm_tf32_kernel<<<dim3(MROWS/128, D_/128), 256>>>(h1, lin2_w, lin2_b, tmp,
                                                       MROWS, D_, 2048, 0, 0);
    ln_add_kernel<<<MROWS, 256>>>(sum, tmp, fu_ng, fu_nb, out);
}

// round 14
// speedup vs baseline: 3.2743x; 1.0632x over previous
#include <cuda_runtime.h>
#include <cuda_bf16.h>
#include <math.h>

// ======================= problem constants =======================
#define L_  1024
#define B_  8
#define D_  512
#define LT_ 32
#define H_  8
#define HD_ 64
#define TOTPOS 2081   // 1024+512+256+128+64+43+32+22

// ======================= scratch (static device memory) =========
__device__ float g_sent[B_*D_];
__device__ float g_scores[B_*L_];
__device__ int   g_vmask[B_*L_];
__device__ int   g_tmask[B_*LT_];
__device__ int   g_ecmask[B_*L_];
__device__ int   g_kmask[TOTPOS*B_];
__device__ float g_keys[TOTPOS*B_*D_];
__device__ float g_qkv[8192*1536];     // also reused as cc KV buffer (12288*1024)
__device__ float g_q[8192*512];
__device__ float g_attn[8192*512];
__device__ float g_tmp[8192*512];
__device__ float g_xec[8192*512];
__device__ float g_total[8192*512];
__device__ float g_xcc[8192*512];
__device__ float g_sum[8192*512];
__device__ float g_h1[8192*2048];

// ======================= mask dtype conversion ==================
__global__ void mask_convert_kernel(const unsigned char* __restrict__ raw,
                                    int* __restrict__ out, int n)
{
    int i = blockIdx.x * blockDim.x + threadIdx.x;
    if (i >= n) return;
    int v;
    if (raw[1] == 1) {                // 1-byte bool
        v = raw[i] != 0;
    } else if (raw[0] == 1) {         // int32
        v = ((const int*)raw)[i] != 0;
    } else {                          // float32
        v = ((const float*)raw)[i] != 0.0f;
    }
    out[i] = v;
}

// ======================= sentence pooling =======================
__global__ void sent_kernel(const float* __restrict__ txt, const int* __restrict__ tmask,
                            const float* __restrict__ wts_w, const float* __restrict__ wts_b,
                            float* __restrict__ sent)
{
    __shared__ float aw[LT_];
    int b = blockIdx.x;
    int t = threadIdx.x;            // 512 threads
    int warp = t >> 5, lane = t & 31;
    for (int tok = warp; tok < LT_; tok += 16) {
        float s = 0.f;
        for (int d = lane; d < D_; d += 32)
            s += txt[((size_t)tok * B_ + b) * D_ + d] * wts_w[d];
        #pragma unroll
        for (int off = 16; off; off >>= 1) s += __shfl_xor_sync(0xffffffffu, s, off);
        if (lane == 0) {
            s += wts_b[0];
            if (!tmask[b * LT_ + tok]) s = -1e9f;
            aw[tok] = s;
        }
    }
    __syncthreads();
    if (t == 0) {
        float mx = -3e38f;
        for (int i = 0; i < LT_; i++) mx = fmaxf(mx, aw[i]);
        float sum = 0.f;
        for (int i = 0; i < LT_; i++) { aw[i] = __expf(aw[i] - mx); sum += aw[i]; }
        float inv = 1.f / sum;
        for (int i = 0; i < LT_; i++) aw[i] *= inv;
    }
    __syncthreads();
    float s = 0.f;
    for (int tok = 0; tok < LT_; tok++)
        s += aw[tok] * txt[((size_t)tok * B_ + b) * D_ + t];
    sent[b * D_ + t] = s;
}

// ======================= relevance scores =======================
__global__ void score_kernel(const float* __restrict__ x, const float* __restrict__ sent,
                             const int* __restrict__ vmask, float* __restrict__ scores)
{
    int l = blockIdx.x, b = blockIdx.y;
    int t = threadIdx.x;            // 128
    __shared__ float r4[4];
    float s = 0.f;
    for (int d = t; d < D_; d += 128)
        s += x[((size_t)l * B_ + b) * D_ + d] * sent[b * D_ + d];
    #pragma unroll
    for (int off = 16; off; off >>= 1) s += __shfl_xor_sync(0xffffffffu, s, off);
    if ((t & 31) == 0) r4[t >> 5] = s;
    __syncthreads();
    if (t == 0) {
        s = r4[0] + r4[1] + r4[2] + r4[3];
        scores[b * L_ + l] = vmask[b * L_ + l] ? s : -1e9f;
    }
}

// ======================= top-k (k=512) via bitonic sort =========
__global__ void topk_kernel(const float* __restrict__ scores, int* __restrict__ ecmask)
{
    __shared__ float sv[L_];
    __shared__ int cnt;
    int b = blockIdx.x, t = threadIdx.x;   // 512 threads
    sv[t] = scores[b * L_ + t];
    sv[t + 512] = scores[b * L_ + t + 512];
    if (t == 0) cnt = 0;
    __syncthreads();
    for (int k = 2; k <= L_; k <<= 1) {
        for (int j = k >> 1; j > 0; j >>= 1) {
            for (int i = t; i < L_; i += 512) {
                int ixj = i ^ j;
                if (ixj > i) {
                    bool up = ((i & k) == 0);
                    float a = sv[i], c = sv[ixj];
                    if ((a > c) == up) { sv[i] = c; sv[ixj] = a; }
                }
            }
            __syncthreads();
        }
    }
    float thr = sv[512];
    for (int i = t; i < L_; i += 512) {
        float sc = scores[b * L_ + i];
        int ig = 1;
        if (sc > thr) { ig = 0; atomicAdd(&cnt, 1); }
        ecmask[b * L_ + i] = ig;
    }
    __syncthreads();
    if (t == 0) {
        int need = 512 - cnt;
        for (int i = 0; i < L_ && need > 0; i++) {
            if (scores[b * L_ + i] == thr && ecmask[b * L_ + i]) {
                ecmask[b * L_ + i] = 0; need--;
            }
        }
    }
}

// ======================= max-pool keys ==========================
__global__ void pool_kernel(const float* __restrict__ x, const int* __restrict__ vmask,
                            float* __restrict__ keys, int* __restrict__ kmask,
                            int s, int posoff)
{
    int p = blockIdx.x, b = blockIdx.y, d = threadIdx.x;  // 512 threads
    int l0 = p * s;
    float mx = (l0 + s > L_) ? 0.0f : -3.0e38f;  // zero-pad participates in max
    int lend = l0 + s; if (lend > L_) lend = L_;
    for (int l = l0; l < lend; l++)
        mx = fmaxf(mx, x[((size_t)l * B_ + b) * D_ + d]);
    keys[((size_t)(posoff + p) * B_ + b) * D_ + d] = mx;
    if (d == 0) {
        int any = 0;
        for (int l = l0; l < lend; l++) any |= vmask[b * L_ + l];
        kmask[(posoff + p) * B_ + b] = !any;   // 1 = ignore
    }
}

// ======================= tf32 helpers ===========================
__device__ __forceinline__ unsigned f2tf(float f)
{
    unsigned u;
    asm("cvt.rna.tf32.f32 %0, %1;" : "=r"(u) : "f"(f));
    return u;
}

#define MMA_TF32(C, a0, a1, a2, a3, b0, b1)                                  \
    asm volatile(                                                            \
        "mma.sync.aligned.m16n8k8.row.col.f32.tf32.tf32.f32 "                \
        "{%0,%1,%2,%3}, {%4,%5,%6,%7}, {%8,%9}, {%0,%1,%2,%3};"              \
        : "+f"((C)[0]), "+f"((C)[1]), "+f"((C)[2]), "+f"((C)[3])             \
        : "r"(a0), "r"(a1), "r"(a2), "r"(a3), "r"(b0), "r"(b1))

// ======================= tf32 GEMM: C = A(MxK) @ W(NxK)^T + bias =
// block 128x128, BK=16, 256 threads (8 warps in 2x4), mma.m16n8k8.tf32
// Software-pipelined: register prefetch of tile k+1 + double-buffered smem,
// single __syncthreads per K-iteration.
__global__ __launch_bounds__(256, 2)
void gemm_tf32_kernel(const float* __restrict__ A, const float* __restrict__ W,
                      const float* __restrict__ bias, float* __restrict__ C,
                      int M, int N, int K, int doRelu, int doAcc)
{
    __shared__ unsigned As[2][16][132];   // [buf][k][m]
    __shared__ unsigned Bs[2][16][132];   // [buf][k][n]
    int bm = blockIdx.x * 128;
    int bn = blockIdx.y * 128;
    int tid = threadIdx.x;
    int wid = tid >> 5, lane = tid & 31;
    int g = lane >> 2, tig = lane & 3;
    int wm = (wid & 1) * 64;
    int wn = (wid >> 1) * 32;

    float c[4][4][4];
    #pragma unroll
    for (int mi = 0; mi < 4; mi++)
        #pragma unroll
        for (int ni = 0; ni < 4; ni++)
            #pragma unroll
            for (int r = 0; r < 4; r++) c[mi][ni][r] = 0.f;

    int lrow = tid >> 2;          // 0..63
    int lcol = (tid & 3) * 4;     // 0,4,8,12

    float4 avp[2], wvp[2];
    // prologue: load tile 0 into regs, stage into buffer 0
    #pragma unroll
    for (int h = 0; h < 2; h++) {
        int r = lrow + h * 64;
        avp[h] = make_float4(0.f, 0.f, 0.f, 0.f);
        if (bm + r < M)
            avp[h] = *(const float4*)(A + (size_t)(bm + r) * K + lcol);
        wvp[h] = *(const float4*)(W + (size_t)(bn + r) * K + lcol);
    }
    #pragma unroll
    for (int h = 0; h < 2; h++) {
        int r = lrow + h * 64;
        As[0][lcol][r]   = f2tf(avp[h].x);
        As[0][lcol+1][r] = f2tf(avp[h].y);
        As[0][lcol+2][r] = f2tf(avp[h].z);
        As[0][lcol+3][r] = f2tf(avp[h].w);
        Bs[0][lcol][r]   = f2tf(wvp[h].x);
        Bs[0][lcol+1][r] = f2tf(wvp[h].y);
        Bs[0][lcol+2][r] = f2tf(wvp[h].z);
        Bs[0][lcol+3][r] = f2tf(wvp[h].w);
    }
    __syncthreads();

    int nIter = K >> 4;
    int buf = 0;
    for (int it = 0; it < nIter; it++) {
        // prefetch tile it+1 into registers (overlaps with MMA below)
        bool more = (it + 1 < nIter);
        if (more) {
            int k0n = (it + 1) << 4;
            #pragma unroll
            for (int h = 0; h < 2; h++) {
                int r = lrow + h * 64;
                avp[h] = make_float4(0.f, 0.f, 0.f, 0.f);
                if (bm + r < M)
                    avp[h] = *(const float4*)(A + (size_t)(bm + r) * K + k0n + lcol);
                wvp[h] = *(const float4*)(W + (size_t)(bn + r) * K + k0n + lcol);
            }
        }
        // MMA on current buffer
        #pragma unroll
        for (int kk = 0; kk < 16; kk += 8) {
            unsigned bf[4][2];
            #pragma unroll
            for (int ni = 0; ni < 4; ni++) {
                int n = wn + ni * 8 + g;
                bf[ni][0] = Bs[buf][kk + tig][n];
                bf[ni][1] = Bs[buf][kk + tig + 4][n];
            }
            #pragma unroll
            for (int mi = 0; mi < 4; mi++) {
                int m = wm + mi * 16 + g;
                unsigned a0 = As[buf][kk + tig][m];
                unsigned a1 = As[buf][kk + tig][m + 8];
                unsigned a2 = As[buf][kk + tig + 4][m];
                unsigned a3 = As[buf][kk + tig + 4][m + 8];
                #pragma unroll
                for (int ni = 0; ni < 4; ni++)
                    MMA_TF32(c[mi][ni], a0, a1, a2, a3, bf[ni][0], bf[ni][1]);
            }
        }
        // stage prefetched tile into the other buffer
        if (more) {
            int ob = buf ^ 1;
            #pragma unroll
            for (int h = 0; h < 2; h++) {
                int r = lrow + h * 64;
                As[ob][lcol][r]   = f2tf(avp[h].x);
                As[ob][lcol+1][r] = f2tf(avp[h].y);
                As[ob][lcol+2][r] = f2tf(avp[h].z);
                As[ob][lcol+3][r] = f2tf(avp[h].w);
                Bs[ob][lcol][r]   = f2tf(wvp[h].x);
                Bs[ob][lcol+1][r] = f2tf(wvp[h].y);
                Bs[ob][lcol+2][r] = f2tf(wvp[h].z);
                Bs[ob][lcol+3][r] = f2tf(wvp[h].w);
            }
            __syncthreads();
        }
        buf ^= 1;
    }

    // epilogue
    #pragma unroll
    for (int mi = 0; mi < 4; mi++) {
        #pragma unroll
        for (int ni = 0; ni < 4; ni++) {
            int col = bn + wn + ni * 8 + tig * 2;
            float b0 = bias[col], b1 = bias[col + 1];
            #pragma unroll
            for (int h = 0; h < 2; h++) {
                int row = bm + wm + mi * 16 + g + h * 8;
                if (row >= M) continue;
                float v0 = c[mi][ni][h * 2]     + b0;
                float v1 = c[mi][ni][h * 2 + 1] + b1;
                if (doRelu) { v0 = fmaxf(v0, 0.f); v1 = fmaxf(v1, 0.f); }
                float* p = C + (size_t)row * N + col;
                if (doAcc) { p[0] += v0; p[1] += v1; }
                else       { p[0] = v0;  p[1] = v1;  }
            }
        }
    }
}

// ======================= MMA flash attention ====================
// grid (L/64, B*H), 128 threads = 4 warps, each warp 16 q rows.
// S = Q K^T and O += P V via mma.m16n8k8.tf32.  K-tile = 64 keys.
// P is staged through the (dead) K smem buffer to convert C->A layout.
__global__ __launch_bounds__(128)
void attn_mma_kernel(const float* __restrict__ Q, int ldq,
                     const float* __restrict__ K, int ldk,
                     const float* __restrict__ V, int ldv,
                     const int* __restrict__ mask, int msj, int msb,
                     float* __restrict__ O, int ldo,
                     int Lk, float scale)
{
    __shared__ float ks[64][68];
    __shared__ float vs[64][68];
    __shared__ int   msk[64];

    int b = blockIdx.y & 7;
    int h = blockIdx.y >> 3;
    int q0 = blockIdx.x * 64;
    int tid = threadIdx.x;
    int w = tid >> 5, lane = tid & 31;
    int g = lane >> 2, tig = lane & 3;
    int r0 = w * 16 + g;      // local q row (first)
    int r1 = r0 + 8;          // local q row (second)

    // Q fragments, register-resident for whole kernel
    unsigned qf[8][4];
    {
        const float* q0p = Q + ((size_t)(q0 + r0) * B_ + b) * ldq + h * HD_;
        const float* q1p = Q + ((size_t)(q0 + r1) * B_ + b) * ldq + h * HD_;
        #pragma unroll
        for (int kc = 0; kc < 8; kc++) {
            qf[kc][0] = f2tf(q0p[kc * 8 + tig]);
            qf[kc][1] = f2tf(q1p[kc * 8 + tig]);
            qf[kc][2] = f2tf(q0p[kc * 8 + tig + 4]);
            qf[kc][3] = f2tf(q1p[kc * 8 + tig + 4]);
        }
    }

    float oacc[8][4];
    #pragma unroll
    for (int ni = 0; ni < 8; ni++)
        #pragma unroll
        for (int r = 0; r < 4; r++) oacc[ni][r] = 0.f;
    float m0 = -3.0e38f, m1 = -3.0e38f, l0s = 0.f, l1s = 0.f;

    for (int j0 = 0; j0 < Lk; j0 += 64) {
        // load K,V tile (zero-filled out of range) + mask
        #pragma unroll
        for (int it = 0; it < 8; it++) {
            int id = tid + it * 128;       // 0..1023 float4 slots
            int row = id >> 4, c4 = (id & 15) * 4;
            int j = j0 + row;
            float4 kv = make_float4(0.f,0.f,0.f,0.f), vv = make_float4(0.f,0.f,0.f,0.f);
            if (j < Lk) {
                kv = *(const float4*)(K + ((size_t)j * B_ + b) * ldk + h * HD_ + c4);
                vv = *(const float4*)(V + ((size_t)j * B_ + b) * ldv + h * HD_ + c4);
            }
            *(float4*)&ks[row][c4] = kv;
            *(float4*)&vs[row][c4] = vv;
        }
        if (tid < 64)
            msk[tid] = (j0 + tid < Lk) ? mask[(size_t)(j0 + tid) * msj + (size_t)b * msb] : 1;
        __syncthreads();

        // S = Q K^T  (A = Q regs, B = K from smem)
        float s[8][4];
        #pragma unroll
        for (int ni = 0; ni < 8; ni++)
            #pragma unroll
            for (int r = 0; r < 4; r++) s[ni][r] = 0.f;
        #pragma unroll
        for (int kc = 0; kc < 8; kc++) {
            #pragma unroll
            for (int ni = 0; ni < 8; ni++) {
                unsigned b0 = f2tf(ks[ni * 8 + g][kc * 8 + tig]);
                unsigned b1 = f2tf(ks[ni * 8 + g][kc * 8 + tig + 4]);
                MMA_TF32(s[ni], qf[kc][0], qf[kc][1], qf[kc][2], qf[kc][3], b0, b1);
            }
        }
        __syncthreads();   // all warps finished reading ks; it becomes the P buffer

        // mask + scale + online softmax (C layout: rows r0/r1, cols ni*8+2tig{,+1})
        float tm0 = -3.0e38f, tm1 = -3.0e38f;
        #pragma unroll
        for (int ni = 0; ni < 8; ni++) {
            int ja = ni * 8 + 2 * tig;
            bool ia = msk[ja] != 0;
            bool ib = msk[ja + 1] != 0;
            s[ni][0] = ia ? -3.0e38f : s[ni][0] * scale;
            s[ni][1] = ib ? -3.0e38f : s[ni][1] * scale;
            s[ni][2] = ia ? -3.0e38f : s[ni][2] * scale;
            s[ni][3] = ib ? -3.0e38f : s[ni][3] * scale;
            tm0 = fmaxf(tm0, fmaxf(s[ni][0], s[ni][1]));
            tm1 = fmaxf(tm1, fmaxf(s[ni][2], s[ni][3]));
        }
        tm0 = fmaxf(tm0, __shfl_xor_sync(0xffffffffu, tm0, 1));
        tm0 = fmaxf(tm0, __shfl_xor_sync(0xffffffffu, tm0, 2));
        tm1 = fmaxf(tm1, __shfl_xor_sync(0xffffffffu, tm1, 1));
        tm1 = fmaxf(tm1, __shfl_xor_sync(0xffffffffu, tm1, 2));
        float mn0 = fmaxf(m0, tm0), mn1 = fmaxf(m1, tm1);
        float ps0 = 0.f, ps1 = 0.f;
        #pragma unroll
        for (int ni = 0; ni < 8; ni++) {
            s[ni][0] = (s[ni][0] <= -1e37f) ? 0.f : __expf(s[ni][0] - mn0);
            s[ni][1] = (s[ni][1] <= -1e37f) ? 0.f : __expf(s[ni][1] - mn0);
            s[ni][2] = (s[ni][2] <= -1e37f) ? 0.f : __expf(s[ni][2] - mn1);
            s[ni][3] = (s[ni][3] <= -1e37f) ? 0.f : __expf(s[ni][3] - mn1);
            ps0 += s[ni][0] + s[ni][1];
            ps1 += s[ni][2] + s[ni][3];
        }
        ps0 += __shfl_xor_sync(0xffffffffu, ps0, 1);
        ps0 += __shfl_xor_sync(0xffffffffu, ps0, 2);
        ps1 += __shfl_xor_sync(0xffffffffu, ps1, 1);
        ps1 += __shfl_xor_sync(0xffffffffu, ps1, 2);
        float f0 = (mn0 <= -1e37f) ? 1.f : __expf(m0 - mn0);
        float f1 = (mn1 <= -1e37f) ? 1.f : __expf(m1 - mn1);
        m0 = mn0; m1 = mn1;
        l0s = l0s * f0 + ps0;
        l1s = l1s * f1 + ps1;

        // stage P into ks (warp-local rows), rescale O
        #pragma unroll
        for (int ni = 0; ni < 8; ni++) {
            ks[r0][ni * 8 + 2 * tig]     = s[ni][0];
            ks[r0][ni * 8 + 2 * tig + 1] = s[ni][1];
            ks[r1][ni * 8 + 2 * tig]     = s[ni][2];
            ks[r1][ni * 8 + 2 * tig + 1] = s[ni][3];
            oacc[ni][0] *= f0; oacc[ni][1] *= f0;
            oacc[ni][2] *= f1; oacc[ni][3] *= f1;
        }
        __syncwarp();

        // O += P V  (A = P from smem, B = V from smem)
        #pragma unroll
        for (int kc = 0; kc < 8; kc++) {
            unsigned pa0 = f2tf(ks[r0][kc * 8 + tig]);
            unsigned pa1 = f2tf(ks[r1][kc * 8 + tig]);
            unsigned pa2 = f2tf(ks[r0][kc * 8 + tig + 4]);
            unsigned pa3 = f2tf(ks[r1][kc * 8 + tig + 4]);
            #pragma unroll
            for (int ni = 0; ni < 8; ni++) {
                unsigned vb0 = f2tf(vs[kc * 8 + tig][ni * 8 + g]);
                unsigned vb1 = f2tf(vs[kc * 8 + tig + 4][ni * 8 + g]);
                MMA_TF32(oacc[ni], pa0, pa1, pa2, pa3, vb0, vb1);
            }
        }
        __syncthreads();   // done with ks(P)/vs before next tile load
    }

    float i0 = 1.0f / l0s, i1 = 1.0f / l1s;
    #pragma unroll
    for (int ni = 0; ni < 8; ni++) {
        int col = h * HD_ + ni * 8 + 2 * tig;
        float* p0 = O + ((size_t)(q0 + r0) * B_ + b) * ldo + col;
        p0[0] = oacc[ni][0] * i0; p0[1] = oacc[ni][1] * i0;
        float* p1 = O + ((size_t)(q0 + r1) * B_ + b) * ldo + col;
        p1[0] = oacc[ni][2] * i1; p1[1] = oacc[ni][3] * i1;
    }
}

// ======================= layer norm on (a+b) ====================
__device__ __forceinline__ float blockReduceSum256(float v)
{
    __shared__ float sh[8];
    int lane = threadIdx.x & 31, w = threadIdx.x >> 5;
    #pragma unroll
    for (int o = 16; o; o >>= 1) v += __shfl_xor_sync(0xffffffffu, v, o);
    if (lane == 0) sh[w] = v;
    __syncthreads();
    float r = (threadIdx.x < 8) ? sh[threadIdx.x] : 0.f;
    if (w == 0) {
        #pragma unroll
        for (int o = 4; o; o >>= 1) r += __shfl_xor_sync(0xffffffffu, r, o);
        if (lane == 0) sh[0] = r;
    }
    __syncthreads();
    r = sh[0];
    __syncthreads();
    return r;
}

__global__ void ln_add_kernel(const float* __restrict__ a, const float* __restrict__ b,
                              const float* __restrict__ g, const float* __restrict__ bet,
                              float* __restrict__ out)
{
    int row = blockIdx.x, t = threadIdx.x;
    const float* ap = a + (size_t)row * D_;
    const float* bp = b + (size_t)row * D_;
    float v0 = ap[t] + bp[t];
    float v1 = ap[t + 256] + bp[t + 256];
    float mu = blockReduceSum256(v0 + v1) * (1.f / D_);
    float d0 = v0 - mu, d1 = v1 - mu;
    float var = blockReduceSum256(d0 * d0 + d1 * d1) * (1.f / D_);
    float rs = rsqrtf(var + 1e-5f);
    float* op = out + (size_t)row * D_;
    op[t] = d0 * rs * g[t] + bet[t];
    op[t + 256] = d1 * rs * g[t + 256] + bet[t + 256];
}

__global__ void add_kernel(const float* __restrict__ a, const float* __restrict__ b,
                           float* __restrict__ c, int n)
{
    int i = blockIdx.x * blockDim.x + threadIdx.x;
    if (i < n) c[i] = a[i] + b[i];
}

// ======================= host orchestration =====================
extern "C" void kernel_launch(void* const* d_in, const int* in_sizes, int n_in,
                              void* d_out, int out_size)
{
    const float* x        = (const float*)d_in[0];
    const float* txt      = (const float*)d_in[1];
    const unsigned char* vmask_raw = (const unsigned char*)d_in[2];
    const unsigned char* tmask_raw = (const unsigned char*)d_in[3];
    const float* wts_w    = (const float*)d_in[4];
    const float* wts_b    = (const float*)d_in[5];
    const float* ec_in_w  = (const float*)d_in[6];
    const float* ec_in_b  = (const float*)d_in[7];
    const float* ec_out_w = (const float*)d_in[8];
    const float* ec_out_b = (const float*)d_in[9];
    const float* cc_in_w  = (const float*)d_in[10];
    const float* cc_in_b  = (const float*)d_in[11];
    const float* cc_out_w = (const float*)d_in[12];
    const float* cc_out_b = (const float*)d_in[13];
    const float* ec_ng    = (const float*)d_in[14];
    const float* ec_nb    = (const float*)d_in[15];
    const float* cc_ng    = (const float*)d_in[16];
    const float* cc_nb    = (const float*)d_in[17];
    const float* fu_ng    = (const float*)d_in[18];
    const float* fu_nb    = (const float*)d_in[19];
    const float* lin1_w   = (const float*)d_in[20];
    const float* lin1_b   = (const float*)d_in[21];
    const float* lin2_w   = (const float*)d_in[22];
    const float* lin2_b   = (const float*)d_in[23];
    float* out = (float*)d_out;

    float *sent, *scores, *keys, *qkv, *q, *attn, *tmp, *xec, *total, *xcc, *sum, *h1;
    int *vmask, *tmask, *ecmask, *kmask;
    cudaGetSymbolAddress((void**)&sent,   g_sent);
    cudaGetSymbolAddress((void**)&scores, g_scores);
    cudaGetSymbolAddress((void**)&vmask,  g_vmask);
    cudaGetSymbolAddress((void**)&tmask,  g_tmask);
    cudaGetSymbolAddress((void**)&ecmask, g_ecmask);
    cudaGetSymbolAddress((void**)&kmask,  g_kmask);
    cudaGetSymbolAddress((void**)&keys,   g_keys);
    cudaGetSymbolAddress((void**)&qkv,    g_qkv);
    cudaGetSymbolAddress((void**)&q,      g_q);
    cudaGetSymbolAddress((void**)&attn,   g_attn);
    cudaGetSymbolAddress((void**)&tmp,    g_tmp);
    cudaGetSymbolAddress((void**)&xec,    g_xec);
    cudaGetSymbolAddress((void**)&total,  g_total);
    cudaGetSymbolAddress((void**)&xcc,    g_xcc);
    cudaGetSymbolAddress((void**)&sum,    g_sum);
    cudaGetSymbolAddress((void**)&h1,     g_h1);

    const int MROWS = L_ * B_;   // 8192
    const float SCALE = 0.125f;  // 1/sqrt(64)

    // masks
    mask_convert_kernel<<<(B_*L_ + 255)/256, 256>>>(vmask_raw, vmask, B_*L_);
    mask_convert_kernel<<<1, 256>>>(tmask_raw, tmask, B_*LT_);

    // sentence pooling + relevance scores + top-k mask
    sent_kernel<<<B_, 512>>>(txt, tmask, wts_w, wts_b, sent);
    score_kernel<<<dim3(L_, B_), 128>>>(x, sent, vmask, scores);
    topk_kernel<<<B_, 512>>>(scores, ecmask);

    // pooled keys for all 8 strides
    const int S[8]   = {1, 2, 4, 8, 16, 24, 32, 48};
    const int LP[8]  = {1024, 512, 256, 128, 64, 43, 32, 22};
    const int OFF[8] = {0, 1024, 1536, 1792, 1920, 1984, 2027, 2059};
    for (int si = 0; si < 8; si++)
        pool_kernel<<<dim3(LP[si], B_), 512>>>(x, vmask, keys, kmask, S[si], OFF[si]);

    // ===== essential-context self attention =====
    gemm_tf32_kernel<<<dim3(MROWS/128, 1536/128), 256>>>(x, ec_in_w, ec_in_b, qkv,
                                                         MROWS, 1536, D_, 0, 0);
    attn_mma_kernel<<<dim3(L_/64, B_*H_), 128>>>(qkv, 1536, qkv + 512, 1536, qkv + 1024, 1536,
                                                 ecmask, 1, L_, attn, D_, L_, SCALE);
    gemm_tf32_kernel<<<dim3(MROWS/128, D_/128), 256>>>(attn, ec_out_w, ec_out_b, tmp,
                                                       MROWS, D_, D_, 0, 0);
    ln_add_kernel<<<MROWS, 256>>>(x, tmp, ec_ng, ec_nb, xec);

    // ===== multi-stride cross-context attentions =====
    const int GO[4] = {0, 1536, 1920, 2027};
    const int LK[4] = {1536, 384, 107, 54};
    for (int i = 0; i < 4; i++) {
        const float* Wq = cc_in_w + (size_t)i * 3 * D_ * D_;
        const float* Wkv = Wq + (size_t)D_ * D_;           // K and V weights contiguous (1024 rows)
        const float* bq  = cc_in_b + (size_t)i * 3 * D_;
        const float* bkv = bq + D_;                        // K and V biases contiguous
        int mk = LK[i] * B_;
        gemm_tf32_kernel<<<dim3(MROWS/128, D_/128), 256>>>(x, Wq, bq, q, MROWS, D_, D_, 0, 0);
        // fused K+V projection: out ld = 1024, k at col 0, v at col 512 (reuse qkv buffer)
        gemm_tf32_kernel<<<dim3((mk + 127)/128, 1024/128), 256>>>(
            keys + (size_t)GO[i]*B_*D_, Wkv, bkv, qkv, mk, 1024, D_, 0, 0);
        attn_mma_kernel<<<dim3(L_/64, B_*H_), 128>>>(q, D_, qkv, 1024, qkv + 512, 1024,
                                                     kmask + GO[i]*B_, B_, 1,
                                                     attn, D_, LK[i], SCALE);
        gemm_tf32_kernel<<<dim3(MROWS/128, D_/128), 256>>>(attn, cc_out_w + (size_t)i*D_*D_,
                                                           cc_out_b + (size_t)i*D_, total,
                                                           MROWS, D_, D_, 0, (i > 0) ? 1 : 0);
    }
    ln_add_kernel<<<MROWS, 256>>>(x, total, cc_ng, cc_nb, xcc);

    // ===== fusion FFN =====
    add_kernel<<<(MROWS*D_ + 255)/256, 256>>>(xec, xcc, sum, MROWS*D_);
    gemm_tf32_kernel<<<dim3(MROWS/128, 2048/128), 256>>>(sum, lin1_w, lin1_b, h1,
                                                         MROWS, 2048, D_, 1, 0);
    gemm_tf32_kernel<<<dim3(MROWS/128, D_/128), 256>>>(h1, lin2_w, lin2_b, tmp,
                                                       MROWS, D_, 2048, 0, 0);
    ln_add_kernel<<<MROWS, 256>>>(sum, tmp, fu_ng, fu_nb, out);
}

// round 17
// speedup vs baseline: 3.4296x; 1.0474x over previous
#include <cuda_runtime.h>
#include <cuda_bf16.h>
#include <math.h>

// ======================= problem constants =======================
#define L_  1024
#define B_  8
#define D_  512
#define LT_ 32
#define H_  8
#define HD_ 64
#define TOTPOS 2081   // 1024+512+256+128+64+43+32+22

// ======================= scratch (static device memory) =========
__device__ float g_sent[B_*D_];
__device__ float g_scores[B_*L_];
__device__ int   g_vmask[B_*L_];
__device__ int   g_tmask[B_*LT_];
__device__ int   g_ecmask[B_*L_];
__device__ int   g_kmask[TOTPOS*B_];
__device__ float g_keys[TOTPOS*B_*D_];
__device__ float g_qkv[8192*1536];     // also reused as cc KV buffer (12288*1024)
__device__ float g_q[8192*512];
__device__ float g_attn[8192*512];
__device__ float g_tmp[8192*512];
__device__ float g_xec[8192*512];
__device__ float g_total[8192*512];
__device__ float g_xcc[8192*512];
__device__ float g_sum[8192*512];
__device__ float g_h1[8192*2048];

// ======================= mask dtype conversion ==================
__global__ void mask_convert_kernel(const unsigned char* __restrict__ raw,
                                    int* __restrict__ out, int n)
{
    int i = blockIdx.x * blockDim.x + threadIdx.x;
    if (i >= n) return;
    int v;
    if (raw[1] == 1) {                // 1-byte bool
        v = raw[i] != 0;
    } else if (raw[0] == 1) {         // int32
        v = ((const int*)raw)[i] != 0;
    } else {                          // float32
        v = ((const float*)raw)[i] != 0.0f;
    }
    out[i] = v;
}

// ======================= sentence pooling =======================
__global__ void sent_kernel(const float* __restrict__ txt, const int* __restrict__ tmask,
                            const float* __restrict__ wts_w, const float* __restrict__ wts_b,
                            float* __restrict__ sent)
{
    __shared__ float aw[LT_];
    int b = blockIdx.x;
    int t = threadIdx.x;            // 512 threads
    int warp = t >> 5, lane = t & 31;
    for (int tok = warp; tok < LT_; tok += 16) {
        float s = 0.f;
        for (int d = lane; d < D_; d += 32)
            s += txt[((size_t)tok * B_ + b) * D_ + d] * wts_w[d];
        #pragma unroll
        for (int off = 16; off; off >>= 1) s += __shfl_xor_sync(0xffffffffu, s, off);
        if (lane == 0) {
            s += wts_b[0];
            if (!tmask[b * LT_ + tok]) s = -1e9f;
            aw[tok] = s;
        }
    }
    __syncthreads();
    if (t == 0) {
        float mx = -3e38f;
        for (int i = 0; i < LT_; i++) mx = fmaxf(mx, aw[i]);
        float sum = 0.f;
        for (int i = 0; i < LT_; i++) { aw[i] = __expf(aw[i] - mx); sum += aw[i]; }
        float inv = 1.f / sum;
        for (int i = 0; i < LT_; i++) aw[i] *= inv;
    }
    __syncthreads();
    float s = 0.f;
    for (int tok = 0; tok < LT_; tok++)
        s += aw[tok] * txt[((size_t)tok * B_ + b) * D_ + t];
    sent[b * D_ + t] = s;
}

// ======================= relevance scores =======================
__global__ void score_kernel(const float* __restrict__ x, const float* __restrict__ sent,
                             const int* __restrict__ vmask, float* __restrict__ scores)
{
    int l = blockIdx.x, b = blockIdx.y;
    int t = threadIdx.x;            // 128
    __shared__ float r4[4];
    float s = 0.f;
    for (int d = t; d < D_; d += 128)
        s += x[((size_t)l * B_ + b) * D_ + d] * sent[b * D_ + d];
    #pragma unroll
    for (int off = 16; off; off >>= 1) s += __shfl_xor_sync(0xffffffffu, s, off);
    if ((t & 31) == 0) r4[t >> 5] = s;
    __syncthreads();
    if (t == 0) {
        s = r4[0] + r4[1] + r4[2] + r4[3];
        scores[b * L_ + l] = vmask[b * L_ + l] ? s : -1e9f;
    }
}

// ======================= top-k (k=512) via bitonic sort =========
__global__ void topk_kernel(const float* __restrict__ scores, int* __restrict__ ecmask)
{
    __shared__ float sv[L_];
    __shared__ int cnt;
    int b = blockIdx.x, t = threadIdx.x;   // 512 threads
    sv[t] = scores[b * L_ + t];
    sv[t + 512] = scores[b * L_ + t + 512];
    if (t == 0) cnt = 0;
    __syncthreads();
    for (int k = 2; k <= L_; k <<= 1) {
        for (int j = k >> 1; j > 0; j >>= 1) {
            for (int i = t; i < L_; i += 512) {
                int ixj = i ^ j;
                if (ixj > i) {
                    bool up = ((i & k) == 0);
                    float a = sv[i], c = sv[ixj];
                    if ((a > c) == up) { sv[i] = c; sv[ixj] = a; }
                }
            }
            __syncthreads();
        }
    }
    float thr = sv[512];
    for (int i = t; i < L_; i += 512) {
        float sc = scores[b * L_ + i];
        int ig = 1;
        if (sc > thr) { ig = 0; atomicAdd(&cnt, 1); }
        ecmask[b * L_ + i] = ig;
    }
    __syncthreads();
    if (t == 0) {
        int need = 512 - cnt;
        for (int i = 0; i < L_ && need > 0; i++) {
            if (scores[b * L_ + i] == thr && ecmask[b * L_ + i]) {
                ecmask[b * L_ + i] = 0; need--;
            }
        }
    }
}

// ======================= max-pool keys ==========================
__global__ void pool_kernel(const float* __restrict__ x, const int* __restrict__ vmask,
                            float* __restrict__ keys, int* __restrict__ kmask,
                            int s, int posoff)
{
    int p = blockIdx.x, b = blockIdx.y, d = threadIdx.x;  // 512 threads
    int l0 = p * s;
    float mx = (l0 + s > L_) ? 0.0f : -3.0e38f;  // zero-pad participates in max
    int lend = l0 + s; if (lend > L_) lend = L_;
    for (int l = l0; l < lend; l++)
        mx = fmaxf(mx, x[((size_t)l * B_ + b) * D_ + d]);
    keys[((size_t)(posoff + p) * B_ + b) * D_ + d] = mx;
    if (d == 0) {
        int any = 0;
        for (int l = l0; l < lend; l++) any |= vmask[b * L_ + l];
        kmask[(posoff + p) * B_ + b] = !any;   // 1 = ignore
    }
}

// ======================= tf32 helpers ===========================
__device__ __forceinline__ unsigned f2tf(float f)
{
    unsigned u;
    asm("cvt.rna.tf32.f32 %0, %1;" : "=r"(u) : "f"(f));
    return u;
}

#define MMA_TF32(C, a0, a1, a2, a3, b0, b1)                                  \
    asm volatile(                                                            \
        "mma.sync.aligned.m16n8k8.row.col.f32.tf32.tf32.f32 "                \
        "{%0,%1,%2,%3}, {%4,%5,%6,%7}, {%8,%9}, {%0,%1,%2,%3};"              \
        : "+f"((C)[0]), "+f"((C)[1]), "+f"((C)[2]), "+f"((C)[3])             \
        : "r"(a0), "r"(a1), "r"(a2), "r"(a3), "r"(b0), "r"(b1))

// ======================= tf32 GEMM: C = A(MxK) @ W(NxK)^T + bias =
// block 128x128, BK=16, 256 threads (8 warps in 2x4), mma.m16n8k8.tf32
// Software-pipelined: register prefetch of tile k+1 + double-buffered smem,
// single __syncthreads per K-iteration.
__global__ __launch_bounds__(256, 2)
void gemm_tf32_kernel(const float* __restrict__ A, const float* __restrict__ W,
                      const float* __restrict__ bias, float* __restrict__ C,
                      int M, int N, int K, int doRelu, int doAcc)
{
    __shared__ unsigned As[2][16][132];   // [buf][k][m]
    __shared__ unsigned Bs[2][16][132];   // [buf][k][n]
    int bm = blockIdx.x * 128;
    int bn = blockIdx.y * 128;
    int tid = threadIdx.x;
    int wid = tid >> 5, lane = tid & 31;
    int g = lane >> 2, tig = lane & 3;
    int wm = (wid & 1) * 64;
    int wn = (wid >> 1) * 32;

    float c[4][4][4];
    #pragma unroll
    for (int mi = 0; mi < 4; mi++)
        #pragma unroll
        for (int ni = 0; ni < 4; ni++)
            #pragma unroll
            for (int r = 0; r < 4; r++) c[mi][ni][r] = 0.f;

    int lrow = tid >> 2;          // 0..63
    int lcol = (tid & 3) * 4;     // 0,4,8,12

    float4 avp[2], wvp[2];
    #pragma unroll
    for (int h = 0; h < 2; h++) {
        int r = lrow + h * 64;
        avp[h] = make_float4(0.f, 0.f, 0.f, 0.f);
        if (bm + r < M)
            avp[h] = *(const float4*)(A + (size_t)(bm + r) * K + lcol);
        wvp[h] = *(const float4*)(W + (size_t)(bn + r) * K + lcol);
    }
    #pragma unroll
    for (int h = 0; h < 2; h++) {
        int r = lrow + h * 64;
        As[0][lcol][r]   = f2tf(avp[h].x);
        As[0][lcol+1][r] = f2tf(avp[h].y);
        As[0][lcol+2][r] = f2tf(avp[h].z);
        As[0][lcol+3][r] = f2tf(avp[h].w);
        Bs[0][lcol][r]   = f2tf(wvp[h].x);
        Bs[0][lcol+1][r] = f2tf(wvp[h].y);
        Bs[0][lcol+2][r] = f2tf(wvp[h].z);
        Bs[0][lcol+3][r] = f2tf(wvp[h].w);
    }
    __syncthreads();

    int nIter = K >> 4;
    int buf = 0;
    for (int it = 0; it < nIter; it++) {
        bool more = (it + 1 < nIter);
        if (more) {
            int k0n = (it + 1) << 4;
            #pragma unroll
            for (int h = 0; h < 2; h++) {
                int r = lrow + h * 64;
                avp[h] = make_float4(0.f, 0.f, 0.f, 0.f);
                if (bm + r < M)
                    avp[h] = *(const float4*)(A + (size_t)(bm + r) * K + k0n + lcol);
                wvp[h] = *(const float4*)(W + (size_t)(bn + r) * K + k0n + lcol);
            }
        }
        #pragma unroll
        for (int kk = 0; kk < 16; kk += 8) {
            unsigned bf[4][2];
            #pragma unroll
            for (int ni = 0; ni < 4; ni++) {
                int n = wn + ni * 8 + g;
                bf[ni][0] = Bs[buf][kk + tig][n];
                bf[ni][1] = Bs[buf][kk + tig + 4][n];
            }
            #pragma unroll
            for (int mi = 0; mi < 4; mi++) {
                int m = wm + mi * 16 + g;
                unsigned a0 = As[buf][kk + tig][m];
                unsigned a1 = As[buf][kk + tig][m + 8];
                unsigned a2 = As[buf][kk + tig + 4][m];
                unsigned a3 = As[buf][kk + tig + 4][m + 8];
                #pragma unroll
                for (int ni = 0; ni < 4; ni++)
                    MMA_TF32(c[mi][ni], a0, a1, a2, a3, bf[ni][0], bf[ni][1]);
            }
        }
        if (more) {
            int ob = buf ^ 1;
            #pragma unroll
            for (int h = 0; h < 2; h++) {
                int r = lrow + h * 64;
                As[ob][lcol][r]   = f2tf(avp[h].x);
                As[ob][lcol+1][r] = f2tf(avp[h].y);
                As[ob][lcol+2][r] = f2tf(avp[h].z);
                As[ob][lcol+3][r] = f2tf(avp[h].w);
                Bs[ob][lcol][r]   = f2tf(wvp[h].x);
                Bs[ob][lcol+1][r] = f2tf(wvp[h].y);
                Bs[ob][lcol+2][r] = f2tf(wvp[h].z);
                Bs[ob][lcol+3][r] = f2tf(wvp[h].w);
            }
            __syncthreads();
        }
        buf ^= 1;
    }

    #pragma unroll
    for (int mi = 0; mi < 4; mi++) {
        #pragma unroll
        for (int ni = 0; ni < 4; ni++) {
            int col = bn + wn + ni * 8 + tig * 2;
            float b0 = bias[col], b1 = bias[col + 1];
            #pragma unroll
            for (int h = 0; h < 2; h++) {
                int row = bm + wm + mi * 16 + g + h * 8;
                if (row >= M) continue;
                float v0 = c[mi][ni][h * 2]     + b0;
                float v1 = c[mi][ni][h * 2 + 1] + b1;
                if (doRelu) { v0 = fmaxf(v0, 0.f); v1 = fmaxf(v1, 0.f); }
                float* p = C + (size_t)row * N + col;
                if (doAcc) { p[0] += v0; p[1] += v1; }
                else       { p[0] = v0;  p[1] = v1;  }
            }
        }
    }
}

// ======================= MMA flash attention ====================
// grid (L/64, B*H), 128 threads = 4 warps, each warp 16 q rows.
// S = Q K^T and O += P V via mma.m16n8k8.tf32.  K-tile = 64 keys.
// K, V, and staged P live in smem ALREADY tf32-converted (unsigned) so the
// MMA inner loops issue raw LDS only — no per-read CVT.
__global__ __launch_bounds__(128)
void attn_mma_kernel(const float* __restrict__ Q, int ldq,
                     const float* __restrict__ K, int ldk,
                     const float* __restrict__ V, int ldv,
                     const int* __restrict__ mask, int msj, int msb,
                     float* __restrict__ O, int ldo,
                     int Lk, float scale)
{
    __shared__ unsigned ks[64][68];
    __shared__ unsigned vs[64][68];
    __shared__ int      msk[64];

    int b = blockIdx.y & 7;
    int h = blockIdx.y >> 3;
    int q0 = blockIdx.x * 64;
    int tid = threadIdx.x;
    int w = tid >> 5, lane = tid & 31;
    int g = lane >> 2, tig = lane & 3;
    int r0 = w * 16 + g;      // local q row (first)
    int r1 = r0 + 8;          // local q row (second)

    // Q fragments, register-resident for whole kernel
    unsigned qf[8][4];
    {
        const float* q0p = Q + ((size_t)(q0 + r0) * B_ + b) * ldq + h * HD_;
        const float* q1p = Q + ((size_t)(q0 + r1) * B_ + b) * ldq + h * HD_;
        #pragma unroll
        for (int kc = 0; kc < 8; kc++) {
            qf[kc][0] = f2tf(q0p[kc * 8 + tig]);
            qf[kc][1] = f2tf(q1p[kc * 8 + tig]);
            qf[kc][2] = f2tf(q0p[kc * 8 + tig + 4]);
            qf[kc][3] = f2tf(q1p[kc * 8 + tig + 4]);
        }
    }

    float oacc[8][4];
    #pragma unroll
    for (int ni = 0; ni < 8; ni++)
        #pragma unroll
        for (int r = 0; r < 4; r++) oacc[ni][r] = 0.f;
    float m0 = -3.0e38f, m1 = -3.0e38f, l0s = 0.f, l1s = 0.f;

    for (int j0 = 0; j0 < Lk; j0 += 64) {
        // load K,V tile, converting to tf32 ONCE at store time
        #pragma unroll
        for (int it = 0; it < 8; it++) {
            int id = tid + it * 128;       // 0..1023 float4 slots
            int row = id >> 4, c4 = (id & 15) * 4;
            int j = j0 + row;
            float4 kv = make_float4(0.f,0.f,0.f,0.f), vv = make_float4(0.f,0.f,0.f,0.f);
            if (j < Lk) {
                kv = *(const float4*)(K + ((size_t)j * B_ + b) * ldk + h * HD_ + c4);
                vv = *(const float4*)(V + ((size_t)j * B_ + b) * ldv + h * HD_ + c4);
            }
            ks[row][c4]   = f2tf(kv.x);
            ks[row][c4+1] = f2tf(kv.y);
            ks[row][c4+2] = f2tf(kv.z);
            ks[row][c4+3] = f2tf(kv.w);
            vs[row][c4]   = f2tf(vv.x);
            vs[row][c4+1] = f2tf(vv.y);
            vs[row][c4+2] = f2tf(vv.z);
            vs[row][c4+3] = f2tf(vv.w);
        }
        if (tid < 64)
            msk[tid] = (j0 + tid < Lk) ? mask[(size_t)(j0 + tid) * msj + (size_t)b * msb] : 1;
        __syncthreads();

        // S = Q K^T  (A = Q regs, B = K from smem — raw LDS, no CVT)
        float s[8][4];
        #pragma unroll
        for (int ni = 0; ni < 8; ni++)
            #pragma unroll
            for (int r = 0; r < 4; r++) s[ni][r] = 0.f;
        #pragma unroll
        for (int kc = 0; kc < 8; kc++) {
            #pragma unroll
            for (int ni = 0; ni < 8; ni++) {
                unsigned b0 = ks[ni * 8 + g][kc * 8 + tig];
                unsigned b1 = ks[ni * 8 + g][kc * 8 + tig + 4];
                MMA_TF32(s[ni], qf[kc][0], qf[kc][1], qf[kc][2], qf[kc][3], b0, b1);
            }
        }
        __syncthreads();   // all warps finished reading ks; it becomes the P buffer

        // mask + scale + online softmax (C layout: rows r0/r1, cols ni*8+2tig{,+1})
        float tm0 = -3.0e38f, tm1 = -3.0e38f;
        #pragma unroll
        for (int ni = 0; ni < 8; ni++) {
            int ja = ni * 8 + 2 * tig;
            bool ia = msk[ja] != 0;
            bool ib = msk[ja + 1] != 0;
            s[ni][0] = ia ? -3.0e38f : s[ni][0] * scale;
            s[ni][1] = ib ? -3.0e38f : s[ni][1] * scale;
            s[ni][2] = ia ? -3.0e38f : s[ni][2] * scale;
            s[ni][3] = ib ? -3.0e38f : s[ni][3] * scale;
            tm0 = fmaxf(tm0, fmaxf(s[ni][0], s[ni][1]));
            tm1 = fmaxf(tm1, fmaxf(s[ni][2], s[ni][3]));
        }
        tm0 = fmaxf(tm0, __shfl_xor_sync(0xffffffffu, tm0, 1));
        tm0 = fmaxf(tm0, __shfl_xor_sync(0xffffffffu, tm0, 2));
        tm1 = fmaxf(tm1, __shfl_xor_sync(0xffffffffu, tm1, 1));
        tm1 = fmaxf(tm1, __shfl_xor_sync(0xffffffffu, tm1, 2));
        float mn0 = fmaxf(m0, tm0), mn1 = fmaxf(m1, tm1);
        float ps0 = 0.f, ps1 = 0.f;
        #pragma unroll
        for (int ni = 0; ni < 8; ni++) {
            s[ni][0] = (s[ni][0] <= -1e37f) ? 0.f : __expf(s[ni][0] - mn0);
            s[ni][1] = (s[ni][1] <= -1e37f) ? 0.f : __expf(s[ni][1] - mn0);
            s[ni][2] = (s[ni][2] <= -1e37f) ? 0.f : __expf(s[ni][2] - mn1);
            s[ni][3] = (s[ni][3] <= -1e37f) ? 0.f : __expf(s[ni][3] - mn1);
            ps0 += s[ni][0] + s[ni][1];
            ps1 += s[ni][2] + s[ni][3];
        }
        ps0 += __shfl_xor_sync(0xffffffffu, ps0, 1);
        ps0 += __shfl_xor_sync(0xffffffffu, ps0, 2);
        ps1 += __shfl_xor_sync(0xffffffffu, ps1, 1);
        ps1 += __shfl_xor_sync(0xffffffffu, ps1, 2);
        float f0 = (mn0 <= -1e37f) ? 1.f : __expf(m0 - mn0);
        float f1 = (mn1 <= -1e37f) ? 1.f : __expf(m1 - mn1);
        m0 = mn0; m1 = mn1;
        l0s = l0s * f0 + ps0;
        l1s = l1s * f1 + ps1;

        // stage P into ks ALREADY tf32-converted (warp-local rows); rescale O
        #pragma unroll
        for (int ni = 0; ni < 8; ni++) {
            ks[r0][ni * 8 + 2 * tig]     = f2tf(s[ni][0]);
            ks[r0][ni * 8 + 2 * tig + 1] = f2tf(s[ni][1]);
            ks[r1][ni * 8 + 2 * tig]     = f2tf(s[ni][2]);
            ks[r1][ni * 8 + 2 * tig + 1] = f2tf(s[ni][3]);
            oacc[ni][0] *= f0; oacc[ni][1] *= f0;
            oacc[ni][2] *= f1; oacc[ni][3] *= f1;
        }
        __syncwarp();

        // O += P V  (A = P from smem, B = V from smem — raw LDS, no CVT)
        #pragma unroll
        for (int kc = 0; kc < 8; kc++) {
            unsigned pa0 = ks[r0][kc * 8 + tig];
            unsigned pa1 = ks[r1][kc * 8 + tig];
            unsigned pa2 = ks[r0][kc * 8 + tig + 4];
            unsigned pa3 = ks[r1][kc * 8 + tig + 4];
            #pragma unroll
            for (int ni = 0; ni < 8; ni++) {
                unsigned vb0 = vs[kc * 8 + tig][ni * 8 + g];
                unsigned vb1 = vs[kc * 8 + tig + 4][ni * 8 + g];
                MMA_TF32(oacc[ni], pa0, pa1, pa2, pa3, vb0, vb1);
            }
        }
        __syncthreads();   // done with ks(P)/vs before next tile load
    }

    float i0 = 1.0f / l0s, i1 = 1.0f / l1s;
    #pragma unroll
    for (int ni = 0; ni < 8; ni++) {
        int col = h * HD_ + ni * 8 + 2 * tig;
        float* p0 = O + ((size_t)(q0 + r0) * B_ + b) * ldo + col;
        p0[0] = oacc[ni][0] * i0; p0[1] = oacc[ni][1] * i0;
        float* p1 = O + ((size_t)(q0 + r1) * B_ + b) * ldo + col;
        p1[0] = oacc[ni][2] * i1; p1[1] = oacc[ni][3] * i1;
    }
}

// ======================= layer norm on (a+b) ====================
__device__ __forceinline__ float blockReduceSum256(float v)
{
    __shared__ float sh[8];
    int lane = threadIdx.x & 31, w = threadIdx.x >> 5;
    #pragma unroll
    for (int o = 16; o; o >>= 1) v += __shfl_xor_sync(0xffffffffu, v, o);
    if (lane == 0) sh[w] = v;
    __syncthreads();
    float r = (threadIdx.x < 8) ? sh[threadIdx.x] : 0.f;
    if (w == 0) {
        #pragma unroll
        for (int o = 4; o; o >>= 1) r += __shfl_xor_sync(0xffffffffu, r, o);
        if (lane == 0) sh[0] = r;
    }
    __syncthreads();
    r = sh[0];
    __syncthreads();
    return r;
}

__global__ void ln_add_kernel(const float* __restrict__ a, const float* __restrict__ b,
                              const float* __restrict__ g, const float* __restrict__ bet,
                              float* __restrict__ out)
{
    int row = blockIdx.x, t = threadIdx.x;
    const float* ap = a + (size_t)row * D_;
    const float* bp = b + (size_t)row * D_;
    float v0 = ap[t] + bp[t];
    float v1 = ap[t + 256] + bp[t + 256];
    float mu = blockReduceSum256(v0 + v1) * (1.f / D_);
    float d0 = v0 - mu, d1 = v1 - mu;
    float var = blockReduceSum256(d0 * d0 + d1 * d1) * (1.f / D_);
    float rs = rsqrtf(var + 1e-5f);
    float* op = out + (size_t)row * D_;
    op[t] = d0 * rs * g[t] + bet[t];
    op[t + 256] = d1 * rs * g[t + 256] + bet[t + 256];
}

__global__ void add_kernel(const float* __restrict__ a, const float* __restrict__ b,
                           float* __restrict__ c, int n)
{
    int i = blockIdx.x * blockDim.x + threadIdx.x;
    if (i < n) c[i] = a[i] + b[i];
}

// ======================= host orchestration =====================
extern "C" void kernel_launch(void* const* d_in, const int* in_sizes, int n_in,
                              void* d_out, int out_size)
{
    const float* x        = (const float*)d_in[0];
    const float* txt      = (const float*)d_in[1];
    const unsigned char* vmask_raw = (const unsigned char*)d_in[2];
    const unsigned char* tmask_raw = (const unsigned char*)d_in[3];
    const float* wts_w    = (const float*)d_in[4];
    const float* wts_b    = (const float*)d_in[5];
    const float* ec_in_w  = (const float*)d_in[6];
    const float* ec_in_b  = (const float*)d_in[7];
    const float* ec_out_w = (const float*)d_in[8];
    const float* ec_out_b = (const float*)d_in[9];
    const float* cc_in_w  = (const float*)d_in[10];
    const float* cc_in_b  = (const float*)d_in[11];
    const float* cc_out_w = (const float*)d_in[12];
    const float* cc_out_b = (const float*)d_in[13];
    const float* ec_ng    = (const float*)d_in[14];
    const float* ec_nb    = (const float*)d_in[15];
    const float* cc_ng    = (const float*)d_in[16];
    const float* cc_nb    = (const float*)d_in[17];
    const float* fu_ng    = (const float*)d_in[18];
    const float* fu_nb    = (const float*)d_in[19];
    const float* lin1_w   = (const float*)d_in[20];
    const float* lin1_b   = (const float*)d_in[21];
    const float* lin2_w   = (const float*)d_in[22];
    const float* lin2_b   = (const float*)d_in[23];
    float* out = (float*)d_out;

    float *sent, *scores, *keys, *qkv, *q, *attn, *tmp, *xec, *total, *xcc, *sum, *h1;
    int *vmask, *tmask, *ecmask, *kmask;
    cudaGetSymbolAddress((void**)&sent,   g_sent);
    cudaGetSymbolAddress((void**)&scores, g_scores);
    cudaGetSymbolAddress((void**)&vmask,  g_vmask);
    cudaGetSymbolAddress((void**)&tmask,  g_tmask);
    cudaGetSymbolAddress((void**)&ecmask, g_ecmask);
    cudaGetSymbolAddress((void**)&kmask,  g_kmask);
    cudaGetSymbolAddress((void**)&keys,   g_keys);
    cudaGetSymbolAddress((void**)&qkv,    g_qkv);
    cudaGetSymbolAddress((void**)&q,      g_q);
    cudaGetSymbolAddress((void**)&attn,   g_attn);
    cudaGetSymbolAddress((void**)&tmp,    g_tmp);
    cudaGetSymbolAddress((void**)&xec,    g_xec);
    cudaGetSymbolAddress((void**)&total,  g_total);
    cudaGetSymbolAddress((void**)&xcc,    g_xcc);
    cudaGetSymbolAddress((void**)&sum,    g_sum);
    cudaGetSymbolAddress((void**)&h1,     g_h1);

    const int MROWS = L_ * B_;   // 8192
    const float SCALE = 0.125f;  // 1/sqrt(64)

    // masks
    mask_convert_kernel<<<(B_*L_ + 255)/256, 256>>>(vmask_raw, vmask, B_*L_);
    mask_convert_kernel<<<1, 256>>>(tmask_raw, tmask, B_*LT_);

    // sentence pooling + relevance scores + top-k mask
    sent_kernel<<<B_, 512>>>(txt, tmask, wts_w, wts_b, sent);
    score_kernel<<<dim3(L_, B_), 128>>>(x, sent, vmask, scores);
    topk_kernel<<<B_, 512>>>(scores, ecmask);

    // pooled keys for all 8 strides
    const int S[8]   = {1, 2, 4, 8, 16, 24, 32, 48};
    const int LP[8]  = {1024, 512, 256, 128, 64, 43, 32, 22};
    const int OFF[8] = {0, 1024, 1536, 1792, 1920, 1984, 2027, 2059};
    for (int si = 0; si < 8; si++)
        pool_kernel<<<dim3(LP[si], B_), 512>>>(x, vmask, keys, kmask, S[si], OFF[si]);

    // ===== essential-context self attention =====
    gemm_tf32_kernel<<<dim3(MROWS/128, 1536/128), 256>>>(x, ec_in_w, ec_in_b, qkv,
                                                         MROWS, 1536, D_, 0, 0);
    attn_mma_kernel<<<dim3(L_/64, B_*H_), 128>>>(qkv, 1536, qkv + 512, 1536, qkv + 1024, 1536,
                                                 ecmask, 1, L_, attn, D_, L_, SCALE);
    gemm_tf32_kernel<<<dim3(MROWS/128, D_/128), 256>>>(attn, ec_out_w, ec_out_b, tmp,
                                                       MROWS, D_, D_, 0, 0);
    ln_add_kernel<<<MROWS, 256>>>(x, tmp, ec_ng, ec_nb, xec);

    // ===== multi-stride cross-context attentions =====
    const int GO[4] = {0, 1536, 1920, 2027};
    const int LK[4] = {1536, 384, 107, 54};
    for (int i = 0; i < 4; i++) {
        const float* Wq = cc_in_w + (size_t)i * 3 * D_ * D_;
        const float* Wkv = Wq + (size_t)D_ * D_;           // K and V weights contiguous (1024 rows)
        const float* bq  = cc_in_b + (size_t)i * 3 * D_;
        const float* bkv = bq + D_;                        // K and V biases contiguous
        int mk = LK[i] * B_;
        gemm_tf32_kernel<<<dim3(MROWS/128, D_/128), 256>>>(x, Wq, bq, q, MROWS, D_, D_, 0, 0);
        // fused K+V projection: out ld = 1024, k at col 0, v at col 512 (reuse qkv buffer)
        gemm_tf32_kernel<<<dim3((mk + 127)/128, 1024/128), 256>>>(
            keys + (size_t)GO[i]*B_*D_, Wkv, bkv, qkv, mk, 1024, D_, 0, 0);
        attn_mma_kernel<<<dim3(L_/64, B_*H_), 128>>>(q, D_, qkv, 1024, qkv + 512, 1024,
                                                     kmask + GO[i]*B_, B_, 1,
                                                     attn, D_, LK[i], SCALE);
        gemm_tf32_kernel<<<dim3(MROWS/128, D_/128), 256>>>(attn, cc_out_w + (size_t)i*D_*D_,
                                                           cc_out_b + (size_t)i*D_, total,
                                                           MROWS, D_, D_, 0, (i > 0) ? 1 : 0);
    }
    ln_add_kernel<<<MROWS, 256>>>(x, total, cc_ng, cc_nb, xcc);

    // ===== fusion FFN =====
    add_kernel<<<(MROWS*D_ + 255)/256, 256>>>(xec, xcc, sum, MROWS*D_);
    gemm_tf32_kernel<<<dim3(MROWS/128, 2048/128), 256>>>(sum, lin1_w, lin1_b, h1,
                                                         MROWS, 2048, D_, 1, 0);
    gemm_tf32_kernel<<<dim3(MROWS/128, D_/128), 256>>>(h1, lin2_w, lin2_b, tmp,
                                                       MROWS, D_, 2048, 0, 0);
    ln_add_kernel<<<MROWS, 256>>>(sum, tmp, fu_ng, fu_nb, out);
}